// round 13
// baseline (speedup 1.0000x reference)
#include <cuda_runtime.h>
#include <cuda_fp16.h>
#include <math.h>
#include <stdint.h>

typedef __half hf;

// Problem dims
#define BB 2
#define LL 2048
#define DD 512
#define NHH 8
#define NLL 4
#define DMM 2048
#define VV 32000
#define HDD 64
#define MM (BB*LL)          // 4096 rows

// ---------------- PTX helpers ------------------------------------------------
__device__ __forceinline__ uint32_t smem_u32(const void* p) {
    uint32_t a;
    asm("{ .reg .u64 t; cvta.to.shared.u64 t, %1; cvt.u32.u64 %0, t; }"
        : "=r"(a) : "l"(p));
    return a;
}

#define LDSM_X4(r0,r1,r2,r3,addr) \
    asm volatile("ldmatrix.sync.aligned.m8n8.x4.shared.b16 {%0,%1,%2,%3}, [%4];" \
        : "=r"(r0), "=r"(r1), "=r"(r2), "=r"(r3) : "r"(addr))
#define LDSM_X4_T(r0,r1,r2,r3,addr) \
    asm volatile("ldmatrix.sync.aligned.m8n8.x4.trans.shared.b16 {%0,%1,%2,%3}, [%4];" \
        : "=r"(r0), "=r"(r1), "=r"(r2), "=r"(r3) : "r"(addr))
#define MMA16816(d, a, b) \
    asm volatile("mma.sync.aligned.m16n8k16.row.col.f32.f16.f16.f32 " \
        "{%0,%1,%2,%3}, {%4,%5,%6,%7}, {%8,%9}, {%0,%1,%2,%3};" \
        : "+f"((d)[0]), "+f"((d)[1]), "+f"((d)[2]), "+f"((d)[3]) \
        : "r"((a)[0]), "r"((a)[1]), "r"((a)[2]), "r"((a)[3]), \
          "r"((b)[0]), "r"((b)[1]))
#define CP16(dst, src) \
    asm volatile("cp.async.cg.shared.global [%0], [%1], 16;" :: "r"(dst), "l"(src))
#define CP_COMMIT() asm volatile("cp.async.commit_group;" ::: "memory")
#define CP_WAIT2()  asm volatile("cp.async.wait_group 2;" ::: "memory")
#define CP_WAIT1()  asm volatile("cp.async.wait_group 1;" ::: "memory")
#define CP_WAIT0()  asm volatile("cp.async.wait_group 0;" ::: "memory")

// pack two fp32 -> fp16x2 hi word + fp16x2 residual-lo word
__device__ __forceinline__ void split2h(float a, float b, uint32_t &h, uint32_t &l) {
    hf ha = __float2half_rn(a), hb = __float2half_rn(b);
    float ra = a - __half2float(ha);
    float rb = b - __half2float(hb);
    hf la = __float2half_rn(ra), lb = __float2half_rn(rb);
    h = (uint32_t)__half_as_ushort(ha) | ((uint32_t)__half_as_ushort(hb) << 16);
    l = (uint32_t)__half_as_ushort(la) | ((uint32_t)__half_as_ushort(lb) << 16);
}
__device__ __forceinline__ uint32_t pack2h(float a, float b) {
    __half2 p = __floats2half2_rn(a, b);
    return *(uint32_t*)&p;
}

// ---------------- scratch (device globals) -----------------------------------
__device__ float g_h  [MM*DD];        // residual stream
__device__ hf    g_xh [MM*DD];        // activation hi (LN out / attn out)
__device__ hf    g_xl [MM*DD];
__device__ hf    g_mh [MM*DMM];       // mlp hidden hi/lo
__device__ hf    g_ml [MM*DMM];
__device__ hf    g_qh [MM*DD];        // attention Q hi/lo, K, V (fp16)
__device__ hf    g_ql [MM*DD];
__device__ hf    g_kb [MM*DD];
__device__ hf    g_vb [MM*DD];

// transposed fp16 weights [N,K]
#define W_QKV0 0
#define W_OUT0 3145728
#define W_W10  4194304
#define W_W20  8388608
#define W_HEAD 12582912
#define WTOT   28966912
__device__ hf g_w[WTOT];

// ---------------- embedding --------------------------------------------------
__global__ void embed_kernel(const int* __restrict__ x,
                             const float* __restrict__ tok,
                             const float* __restrict__ pos,
                             float* __restrict__ h)
{
    int i = blockIdx.x * blockDim.x + threadIdx.x;
    int d  = i & (DD-1);
    int bl = i / DD;
    int l  = bl & (LL-1);
    h[i] = tok[(size_t)x[bl]*DD + d] + pos[l*DD + d];
}

// ---------------- layernorm (writes fp16 hi/lo split directly) ---------------
__global__ __launch_bounds__(256) void layernorm_kernel(
    const float* __restrict__ x, const float* __restrict__ g,
    const float* __restrict__ b, hf* __restrict__ yh, hf* __restrict__ yl)
{
    __shared__ float red[16];
    __shared__ float stats[2];
    int row = blockIdx.x;
    int tid = threadIdx.x;
    const float2* xr = (const float2*)(x + (size_t)row*DD);
    float2 v = xr[tid];
    float s = v.x + v.y;
    float q = v.x*v.x + v.y*v.y;
    #pragma unroll
    for (int o = 16; o; o >>= 1) {
        s += __shfl_down_sync(0xffffffffu, s, o);
        q += __shfl_down_sync(0xffffffffu, q, o);
    }
    int w = tid >> 5;
    if ((tid & 31) == 0) { red[w] = s; red[w+8] = q; }
    __syncthreads();
    if (tid < 32) {
        s = (tid < 8) ? red[tid]   : 0.f;
        q = (tid < 8) ? red[tid+8] : 0.f;
        #pragma unroll
        for (int o = 4; o; o >>= 1) {
            s += __shfl_down_sync(0xffffffffu, s, o);
            q += __shfl_down_sync(0xffffffffu, q, o);
        }
        if (tid == 0) {
            float mu  = s * (1.0f/DD);
            float var = q * (1.0f/DD) - mu*mu;
            stats[0] = mu;
            stats[1] = rsqrtf(var + 1e-5f);
        }
    }
    __syncthreads();
    float mu = stats[0], inv = stats[1];
    float2 gg = ((const float2*)g)[tid];
    float2 bb = ((const float2*)b)[tid];
    float ox = (v.x - mu)*inv*gg.x + bb.x;
    float oy = (v.y - mu)*inv*gg.y + bb.y;
    uint32_t hh, ll;
    split2h(ox, oy, hh, ll);
    *(uint32_t*)(yh + (size_t)row*DD + 2*tid) = hh;
    *(uint32_t*)(yl + (size_t)row*DD + 2*tid) = ll;
}

// ---------------- weight transpose+convert: [K,N] -> [N,K] fp16 --------------
__global__ __launch_bounds__(256) void tconv_kernel(
    const float* __restrict__ in, hf* __restrict__ w, int K, int N)
{
    __shared__ float t[32][33];
    int n0 = blockIdx.x * 32, k0 = blockIdx.y * 32;
    int tx = threadIdx.x, ty = threadIdx.y;
    #pragma unroll
    for (int i = ty; i < 32; i += 8)
        t[i][tx] = in[(size_t)(k0+i)*N + n0 + tx];
    __syncthreads();
    #pragma unroll
    for (int i = ty; i < 32; i += 8)
        w[(size_t)(n0+i)*K + k0 + tx] = __float2half_rn(t[tx][i]);
}

// ---------------- fp16x2 GEMM: C = (Ah+Al) @ B^T, cp.async 3-stage -----------
// 256 threads, CTA tile 128 x BN. BN=256: warp 64x64; BN=128: warp 32x64.
// fuse: 0=+bias->f32, 1=gelu(+bias)->fp16 hi/lo, 2=+bias+res->f32, 3=plain,
//       4=+bias-> split qkv: Q fp16 hi/lo, K/V fp16 (stride DD)
#define TSTR 72   // smem row stride in fp16 elems (144B: conflict-free ldmatrix)

template<int BN>
__global__ __launch_bounds__(256) void tcgemm(
    const hf* __restrict__ Ahp, const hf* __restrict__ Alp,
    const hf* __restrict__ Bp,
    const float* __restrict__ bias, const float* __restrict__ res,
    float* __restrict__ C, hf* __restrict__ Ch, hf* __restrict__ Cl,
    hf* __restrict__ Kb, hf* __restrict__ Vb,
    int Kd, int Nd, int fuse)
{
    constexpr int NWN = BN/64;          // warps in N dir (4 or 2)
    constexpr int NWM = 8/NWN;          // warps in M dir (2 or 4)
    constexpr int WMT = (128/NWM)/16;   // m16 tiles per warp (4 or 2)
    constexpr int AE = 128*TSTR;
    constexpr int BE = BN*TSTR;
    constexpr int STAGE = 2*AE + BE;    // elems per stage

    extern __shared__ hf sm[];
    uint32_t smb = smem_u32(sm);

    int tid = threadIdx.x, lane = tid & 31, wid = tid >> 5;
    int m0w = (wid / NWN) * (WMT*16);
    int n0w = (wid % NWN) * 64;
    int bn0  = blockIdx.x * BN;
    int row0 = blockIdx.y * 128;

    float acc[WMT][8][4];
    #pragma unroll
    for (int i = 0; i < WMT; i++)
        #pragma unroll
        for (int j = 0; j < 8; j++)
            #pragma unroll
            for (int k = 0; k < 4; k++) acc[i][j][k] = 0.f;

    int kseg = Kd >> 6;

    auto load_stage = [&](int buf, int kk) {
        uint32_t sb = smb + buf*STAGE*2;
        #pragma unroll
        for (int p = 0; p < 4; p++) {
            int id = tid + (p<<8); int r = id>>3, cc = (id&7)<<3;
            CP16(sb + (r*TSTR + cc)*2,
                 Ahp + (size_t)(row0+r)*Kd + kk + cc);
        }
        #pragma unroll
        for (int p = 0; p < 4; p++) {
            int id = tid + (p<<8); int r = id>>3, cc = (id&7)<<3;
            CP16(sb + (AE + r*TSTR + cc)*2,
                 Alp + (size_t)(row0+r)*Kd + kk + cc);
        }
        #pragma unroll
        for (int p = 0; p < BN/32; p++) {
            int id = tid + (p<<8); int r = id>>3, cc = (id&7)<<3;
            CP16(sb + (2*AE + r*TSTR + cc)*2,
                 Bp + (size_t)(bn0+r)*Kd + kk + cc);
        }
    };

    load_stage(0, 0);
    CP_COMMIT();
    load_stage(1, 64);
    CP_COMMIT();

    for (int c = 0; c < kseg; c++) {
        if (c + 2 < kseg) {
            load_stage((c+2)%3, (c+2)<<6);
            CP_COMMIT();
            CP_WAIT2();
        } else if (c + 1 < kseg) {
            CP_WAIT1();
        } else {
            CP_WAIT0();
        }
        __syncthreads();

        uint32_t ab  = smb + (c%3)*STAGE*2;
        uint32_t alb = ab + AE*2;
        uint32_t bbb = ab + 2*AE*2;

        #pragma unroll
        for (int ks = 0; ks < 4; ks++) {
            uint32_t ah4[WMT][4], al4[WMT][4];
            int aoff = ((m0w + (lane & 15))*TSTR + ks*16 + ((lane >> 4) << 3)) * 2;
            #pragma unroll
            for (int mt = 0; mt < WMT; mt++) {
                LDSM_X4(ah4[mt][0],ah4[mt][1],ah4[mt][2],ah4[mt][3],
                        ab  + aoff + mt*16*TSTR*2);
                LDSM_X4(al4[mt][0],al4[mt][1],al4[mt][2],al4[mt][3],
                        alb + aoff + mt*16*TSTR*2);
            }
            int boff = ((n0w + ((lane >> 4) << 3) + (lane & 7))*TSTR +
                        ks*16 + (((lane >> 3) & 1) << 3)) * 2;
            #pragma unroll
            for (int nt2 = 0; nt2 < 4; nt2++) {
                uint32_t b4[4];
                LDSM_X4(b4[0],b4[1],b4[2],b4[3], bbb + boff + nt2*16*TSTR*2);
                uint32_t b01[2]={b4[0],b4[1]}, b23[2]={b4[2],b4[3]};
                #pragma unroll
                for (int mt = 0; mt < WMT; mt++) {
                    MMA16816(acc[mt][2*nt2],   ah4[mt], b01);
                    MMA16816(acc[mt][2*nt2+1], ah4[mt], b23);
                }
                #pragma unroll
                for (int mt = 0; mt < WMT; mt++) {
                    MMA16816(acc[mt][2*nt2],   al4[mt], b01);
                    MMA16816(acc[mt][2*nt2+1], al4[mt], b23);
                }
            }
        }
        __syncthreads();
    }

    // epilogue
    #pragma unroll
    for (int mt = 0; mt < WMT; mt++) {
        int r0 = row0 + m0w + mt*16 + (lane >> 2);
        #pragma unroll
        for (int nt = 0; nt < 8; nt++) {
            int col = bn0 + n0w + nt*8 + ((lane & 3) << 1);
            float2 v0 = make_float2(acc[mt][nt][0], acc[mt][nt][1]);
            float2 v1 = make_float2(acc[mt][nt][2], acc[mt][nt][3]);
            if (fuse != 3) {
                float2 bv = *(const float2*)(bias + col);
                v0.x += bv.x; v0.y += bv.y;
                v1.x += bv.x; v1.y += bv.y;
            }
            if (fuse == 4) {
                if (col < DD) {
                    uint32_t h0, l0, h1, l1;
                    split2h(v0.x, v0.y, h0, l0);
                    split2h(v1.x, v1.y, h1, l1);
                    *(uint32_t*)(Ch + (size_t)r0*DD + col)     = h0;
                    *(uint32_t*)(Cl + (size_t)r0*DD + col)     = l0;
                    *(uint32_t*)(Ch + (size_t)(r0+8)*DD + col) = h1;
                    *(uint32_t*)(Cl + (size_t)(r0+8)*DD + col) = l1;
                } else if (col < 2*DD) {
                    *(uint32_t*)(Kb + (size_t)r0*DD + col - DD)     = pack2h(v0.x, v0.y);
                    *(uint32_t*)(Kb + (size_t)(r0+8)*DD + col - DD) = pack2h(v1.x, v1.y);
                } else {
                    *(uint32_t*)(Vb + (size_t)r0*DD + col - 2*DD)     = pack2h(v0.x, v0.y);
                    *(uint32_t*)(Vb + (size_t)(r0+8)*DD + col - 2*DD) = pack2h(v1.x, v1.y);
                }
                continue;
            }
            if (fuse == 1) {
                v0.x = 0.5f*v0.x*(1.0f + erff(v0.x*0.7071067811865475f));
                v0.y = 0.5f*v0.y*(1.0f + erff(v0.y*0.7071067811865475f));
                v1.x = 0.5f*v1.x*(1.0f + erff(v1.x*0.7071067811865475f));
                v1.y = 0.5f*v1.y*(1.0f + erff(v1.y*0.7071067811865475f));
                uint32_t h0, l0, h1, l1;
                split2h(v0.x, v0.y, h0, l0);
                split2h(v1.x, v1.y, h1, l1);
                *(uint32_t*)(Ch + (size_t)r0*Nd + col)     = h0;
                *(uint32_t*)(Cl + (size_t)r0*Nd + col)     = l0;
                *(uint32_t*)(Ch + (size_t)(r0+8)*Nd + col) = h1;
                *(uint32_t*)(Cl + (size_t)(r0+8)*Nd + col) = l1;
                continue;
            }
            if (fuse == 2) {
                float2 r0v = *(const float2*)(res + (size_t)r0*Nd + col);
                float2 r1v = *(const float2*)(res + (size_t)(r0+8)*Nd + col);
                v0.x += r0v.x; v0.y += r0v.y;
                v1.x += r1v.x; v1.y += r1v.y;
            }
            *(float2*)(C + (size_t)r0*Nd + col)     = v0;
            *(float2*)(C + (size_t)(r0+8)*Nd + col) = v1;
        }
    }
}

#define GS256 221184
#define GS128 165888

// ---------------- tensor-core flash attention (fp16 inputs) ------------------
// S = Qh K + Ql K; PV single pass. K/V tiles double-buffered via cp.async.
#define ATQ 128
#define ATK 64
#define SQH 0
#define SQL 9216
#define SK0 18432
// per-buf K/V block = 2*4608 elems; SV = SK + 4608
#define ATTN_SMEM (36864*2)

__global__ __launch_bounds__(256, 2) void attn_kernel(
    const hf* __restrict__ qh, const hf* __restrict__ ql,
    const hf* __restrict__ kb, const hf* __restrict__ vb,
    hf* __restrict__ oh, hf* __restrict__ ol)
{
    extern __shared__ hf smatt[];
    hf* sm = smatt;
    uint32_t smb = smem_u32(sm);

    int q0 = blockIdx.x * ATQ;
    int hh = blockIdx.y;
    int bb = blockIdx.z;
    int bbLL = bb * LL;
    int hoff = hh * HDD;

    int tid = threadIdx.x, lane = tid & 31, wid = tid >> 5;
    int wrow0 = q0 + wid*16;

    // load Q tile (128x64 fp16 hi/lo)
    #pragma unroll
    for (int p = 0; p < 4; p++) {
        int id = tid + (p << 8);
        int r  = id >> 3;
        int c8 = (id & 7) << 3;
        size_t g = (size_t)(bbLL + q0 + r)*DD + hoff + c8;
        *(uint4*)(sm + SQH + r*TSTR + c8) = *(const uint4*)(qh + g);
        *(uint4*)(sm + SQL + r*TSTR + c8) = *(const uint4*)(ql + g);
    }

    auto load_kv = [&](int t, int buf) {
        int k0 = t * ATK;
        uint32_t sk = smb + (SK0 + buf*9216)*2;
        uint32_t sv = sk + 4608*2;
        #pragma unroll
        for (int p = 0; p < 2; p++) {
            int id = tid + (p << 8);
            int r  = id >> 3;
            int c8 = (id & 7) << 3;
            size_t g = (size_t)(bbLL + k0 + r)*DD + hoff + c8;
            CP16(sk + (r*TSTR + c8)*2, kb + g);
            CP16(sv + (r*TSTR + c8)*2, vb + g);
        }
    };

    float Oa[8][4];
    #pragma unroll
    for (int i = 0; i < 8; i++)
        #pragma unroll
        for (int j = 0; j < 4; j++) Oa[i][j] = 0.f;
    float m0 = -1e30f, m1 = -1e30f, l0s = 0.f, l1s = 0.f;

    int qfb = ((wid*16 + (lane & 15))*TSTR + ((lane >> 4) << 3)) * 2;
    int krow = ((lane >> 4) << 3) + (lane & 7);
    int kcol = (((lane >> 3) & 1) << 3);
    int vrow = (((lane >> 3) & 1) << 3) + (lane & 7);
    int vcol = ((lane >> 4) << 3);
    int mr   = lane >> 2;
    int mc2  = (lane & 3) << 1;

    int ntiles = (q0 + ATQ) / ATK;
    load_kv(0, 0);
    CP_COMMIT();

    for (int t = 0; t < ntiles; t++) {
        int k0 = t * ATK;
        if (t + 1 < ntiles) {
            load_kv(t+1, (t+1) & 1);
            CP_COMMIT();
            CP_WAIT1();
        } else {
            CP_WAIT0();
        }
        __syncthreads();

        if (k0 <= wrow0 + 15) {
            uint32_t skb = smb + (SK0 + (t&1)*9216)*2;
            uint32_t svb = skb + 4608*2;

            // ---- S = Qh K + Ql K ----
            float Sa[8][4];
            #pragma unroll
            for (int i = 0; i < 8; i++)
                #pragma unroll
                for (int j = 0; j < 4; j++) Sa[i][j] = 0.f;

            #pragma unroll
            for (int ks = 0; ks < 4; ks++) {
                uint32_t qhf[4], qlf[4];
                LDSM_X4(qhf[0],qhf[1],qhf[2],qhf[3], smb + SQH*2 + qfb + ks*32);
                LDSM_X4(qlf[0],qlf[1],qlf[2],qlf[3], smb + SQL*2 + qfb + ks*32);
                #pragma unroll
                for (int np = 0; np < 4; np++) {
                    uint32_t kf[4];
                    LDSM_X4(kf[0],kf[1],kf[2],kf[3],
                            skb + ((np*16 + krow)*TSTR + kcol)*2 + ks*32);
                    uint32_t b01[2] = {kf[0],kf[1]}, b23[2] = {kf[2],kf[3]};
                    MMA16816(Sa[2*np],   qhf, b01);
                    MMA16816(Sa[2*np+1], qhf, b23);
                    MMA16816(Sa[2*np],   qlf, b01);
                    MMA16816(Sa[2*np+1], qlf, b23);
                }
            }

            // scale + causal mask
            #pragma unroll
            for (int nt = 0; nt < 8; nt++)
                #pragma unroll
                for (int j = 0; j < 4; j++) Sa[nt][j] *= 0.125f;
            if (k0 + 63 > wrow0) {
                int r0g = wrow0 + mr, r1g = r0g + 8;
                #pragma unroll
                for (int nt = 0; nt < 8; nt++) {
                    int col = k0 + nt*8 + mc2;
                    if (col   > r0g) Sa[nt][0] = -1e30f;
                    if (col+1 > r0g) Sa[nt][1] = -1e30f;
                    if (col   > r1g) Sa[nt][2] = -1e30f;
                    if (col+1 > r1g) Sa[nt][3] = -1e30f;
                }
            }

            // ---- online softmax in registers ----
            float rx0 = -1e30f, rx1 = -1e30f;
            #pragma unroll
            for (int nt = 0; nt < 8; nt++) {
                rx0 = fmaxf(rx0, fmaxf(Sa[nt][0], Sa[nt][1]));
                rx1 = fmaxf(rx1, fmaxf(Sa[nt][2], Sa[nt][3]));
            }
            rx0 = fmaxf(rx0, __shfl_xor_sync(0xffffffffu, rx0, 1));
            rx0 = fmaxf(rx0, __shfl_xor_sync(0xffffffffu, rx0, 2));
            rx1 = fmaxf(rx1, __shfl_xor_sync(0xffffffffu, rx1, 1));
            rx1 = fmaxf(rx1, __shfl_xor_sync(0xffffffffu, rx1, 2));
            float mn0 = fmaxf(m0, rx0), mn1 = fmaxf(m1, rx1);
            float a0 = __expf(m0 - mn0), a1 = __expf(m1 - mn1);
            float s0 = 0.f, s1 = 0.f;
            #pragma unroll
            for (int nt = 0; nt < 8; nt++) {
                Sa[nt][0] = __expf(Sa[nt][0] - mn0);
                Sa[nt][1] = __expf(Sa[nt][1] - mn0);
                Sa[nt][2] = __expf(Sa[nt][2] - mn1);
                Sa[nt][3] = __expf(Sa[nt][3] - mn1);
                s0 += Sa[nt][0] + Sa[nt][1];
                s1 += Sa[nt][2] + Sa[nt][3];
            }
            s0 += __shfl_xor_sync(0xffffffffu, s0, 1);
            s0 += __shfl_xor_sync(0xffffffffu, s0, 2);
            s1 += __shfl_xor_sync(0xffffffffu, s1, 1);
            s1 += __shfl_xor_sync(0xffffffffu, s1, 2);
            l0s = l0s*a0 + s0;  l1s = l1s*a1 + s1;
            m0 = mn0; m1 = mn1;
            #pragma unroll
            for (int nt = 0; nt < 8; nt++) {
                Oa[nt][0] *= a0; Oa[nt][1] *= a0;
                Oa[nt][2] *= a1; Oa[nt][3] *= a1;
            }

            // ---- O += P V ----
            #pragma unroll
            for (int ks = 0; ks < 4; ks++) {
                uint32_t ph[4];
                ph[0] = pack2h(Sa[2*ks][0],   Sa[2*ks][1]);
                ph[1] = pack2h(Sa[2*ks][2],   Sa[2*ks][3]);
                ph[2] = pack2h(Sa[2*ks+1][0], Sa[2*ks+1][1]);
                ph[3] = pack2h(Sa[2*ks+1][2], Sa[2*ks+1][3]);
                #pragma unroll
                for (int np = 0; np < 4; np++) {
                    uint32_t vf[4];
                    LDSM_X4_T(vf[0],vf[1],vf[2],vf[3],
                              svb + ((ks*16 + vrow)*TSTR + np*16 + vcol)*2);
                    uint32_t b01[2] = {vf[0],vf[1]}, b23[2] = {vf[2],vf[3]};
                    MMA16816(Oa[2*np],   ph, b01);
                    MMA16816(Oa[2*np+1], ph, b23);
                }
            }
        }
        __syncthreads();
    }

    // ---- write output as fp16 hi/lo ----
    float inv0 = 1.0f / l0s, inv1 = 1.0f / l1s;
    size_t r0g = (size_t)bbLL + wrow0 + mr;
    size_t r1g = r0g + 8;
    int cb = hoff + mc2;
    #pragma unroll
    for (int nt = 0; nt < 8; nt++) {
        uint32_t h0, l0, h1, l1;
        split2h(Oa[nt][0]*inv0, Oa[nt][1]*inv0, h0, l0);
        split2h(Oa[nt][2]*inv1, Oa[nt][3]*inv1, h1, l1);
        int col = cb + nt*8;
        *(uint32_t*)(oh + r0g*DD + col) = h0;
        *(uint32_t*)(ol + r0g*DD + col) = l0;
        *(uint32_t*)(oh + r1g*DD + col) = h1;
        *(uint32_t*)(ol + r1g*DD + col) = l1;
    }
}

// ---------------- launcher ----------------------------------------------------
extern "C" void kernel_launch(void* const* d_in, const int* in_sizes, int n_in,
                              void* d_out, int out_size)
{
    const int*   x     = (const int*)  d_in[0];
    const float* tok   = (const float*)d_in[1];
    const float* pos   = (const float*)d_in[2];
    const float* ln1g  = (const float*)d_in[3];
    const float* ln1b  = (const float*)d_in[4];
    const float* qkvw  = (const float*)d_in[5];
    const float* qkvb  = (const float*)d_in[6];
    const float* outw  = (const float*)d_in[7];
    const float* outb  = (const float*)d_in[8];
    const float* ln2g  = (const float*)d_in[9];
    const float* ln2b  = (const float*)d_in[10];
    const float* w1    = (const float*)d_in[11];
    const float* b1    = (const float*)d_in[12];
    const float* w2    = (const float*)d_in[13];
    const float* b2    = (const float*)d_in[14];
    const float* lnfg  = (const float*)d_in[15];
    const float* lnfb  = (const float*)d_in[16];
    const float* headw = (const float*)d_in[17];
    float* out = (float*)d_out;

    float *h;
    hf *xh, *xl, *mh, *ml, *w, *qh, *ql, *kb, *vb;
    cudaGetSymbolAddress((void**)&h,   g_h);
    cudaGetSymbolAddress((void**)&xh,  g_xh);
    cudaGetSymbolAddress((void**)&xl,  g_xl);
    cudaGetSymbolAddress((void**)&mh,  g_mh);
    cudaGetSymbolAddress((void**)&ml,  g_ml);
    cudaGetSymbolAddress((void**)&w,   g_w);
    cudaGetSymbolAddress((void**)&qh,  g_qh);
    cudaGetSymbolAddress((void**)&ql,  g_ql);
    cudaGetSymbolAddress((void**)&kb,  g_kb);
    cudaGetSymbolAddress((void**)&vb,  g_vb);

    cudaFuncSetAttribute(attn_kernel,
        cudaFuncAttributeMaxDynamicSharedMemorySize, ATTN_SMEM);
    cudaFuncSetAttribute(tcgemm<256>,
        cudaFuncAttributeMaxDynamicSharedMemorySize, GS256);
    cudaFuncSetAttribute(tcgemm<128>,
        cudaFuncAttributeMaxDynamicSharedMemorySize, GS128);

    // weight prep: transpose [K,N] -> [N,K] + fp16 convert
    dim3 tb(32, 8);
    for (int i = 0; i < NLL; i++) {
        tconv_kernel<<<dim3(1536/32, 512/32), tb>>>(
            qkvw + (size_t)i*DD*3*DD, w + W_QKV0 + (size_t)i*786432, 512, 1536);
        tconv_kernel<<<dim3(512/32, 512/32), tb>>>(
            outw + (size_t)i*DD*DD, w + W_OUT0 + (size_t)i*262144, 512, 512);
        tconv_kernel<<<dim3(2048/32, 512/32), tb>>>(
            w1 + (size_t)i*DD*DMM, w + W_W10 + (size_t)i*1048576, 512, 2048);
        tconv_kernel<<<dim3(512/32, 2048/32), tb>>>(
            w2 + (size_t)i*DMM*DD, w + W_W20 + (size_t)i*1048576, 2048, 512);
    }
    tconv_kernel<<<dim3(32000/32, 512/32), tb>>>(
        headw, w + W_HEAD, 512, 32000);

    embed_kernel<<<(MM*DD)/256, 256>>>(x, tok, pos, h);

    for (int i = 0; i < NLL; i++) {
        // attn block
        layernorm_kernel<<<MM, 256>>>(h, ln1g + i*DD, ln1b + i*DD, xh, xl);
        tcgemm<256><<<dim3(1536/256, MM/128), 256, GS256>>>(
            xh, xl, w + W_QKV0 + (size_t)i*786432,
            qkvb + (size_t)i*3*DD, nullptr, nullptr, qh, ql, kb, vb,
            512, 1536, 4);
        attn_kernel<<<dim3(LL/ATQ, NHH, BB), 256, ATTN_SMEM>>>(
            qh, ql, kb, vb, xh, xl);
        tcgemm<128><<<dim3(512/128, MM/128), 256, GS128>>>(
            xh, xl, w + W_OUT0 + (size_t)i*262144,
            outb + (size_t)i*DD, h, h, nullptr, nullptr, nullptr, nullptr,
            512, 512, 2);
        // mlp block
        layernorm_kernel<<<MM, 256>>>(h, ln2g + i*DD, ln2b + i*DD, xh, xl);
        tcgemm<256><<<dim3(2048/256, MM/128), 256, GS256>>>(
            xh, xl, w + W_W10 + (size_t)i*1048576,
            b1 + (size_t)i*DMM, nullptr, nullptr, mh, ml, nullptr, nullptr,
            512, 2048, 1);
        tcgemm<128><<<dim3(512/128, MM/128), 256, GS128>>>(
            mh, ml, w + W_W20 + (size_t)i*1048576,
            b2 + (size_t)i*DD, h, h, nullptr, nullptr, nullptr, nullptr,
            2048, 512, 2);
    }

    layernorm_kernel<<<MM, 256>>>(h, lnfg, lnfb, xh, xl);
    tcgemm<256><<<dim3(VV/256, MM/128), 256, GS256>>>(
        xh, xl, w + W_HEAD,
        nullptr, nullptr, out, nullptr, nullptr, nullptr, nullptr,
        512, VV, 3);
}

// round 14
// speedup vs baseline: 1.1861x; 1.1861x over previous
#include <cuda_runtime.h>
#include <cuda_fp16.h>
#include <math.h>
#include <stdint.h>

typedef __half hf;

// Problem dims
#define BB 2
#define LL 2048
#define DD 512
#define NHH 8
#define NLL 4
#define DMM 2048
#define VV 32000
#define HDD 64
#define MM (BB*LL)          // 4096 rows

// ---------------- PTX helpers ------------------------------------------------
__device__ __forceinline__ uint32_t smem_u32(const void* p) {
    uint32_t a;
    asm("{ .reg .u64 t; cvta.to.shared.u64 t, %1; cvt.u32.u64 %0, t; }"
        : "=r"(a) : "l"(p));
    return a;
}

#define LDSM_X4(r0,r1,r2,r3,addr) \
    asm volatile("ldmatrix.sync.aligned.m8n8.x4.shared.b16 {%0,%1,%2,%3}, [%4];" \
        : "=r"(r0), "=r"(r1), "=r"(r2), "=r"(r3) : "r"(addr))
#define LDSM_X4_T(r0,r1,r2,r3,addr) \
    asm volatile("ldmatrix.sync.aligned.m8n8.x4.trans.shared.b16 {%0,%1,%2,%3}, [%4];" \
        : "=r"(r0), "=r"(r1), "=r"(r2), "=r"(r3) : "r"(addr))
#define MMA16816(d, a, b) \
    asm volatile("mma.sync.aligned.m16n8k16.row.col.f32.f16.f16.f32 " \
        "{%0,%1,%2,%3}, {%4,%5,%6,%7}, {%8,%9}, {%0,%1,%2,%3};" \
        : "+f"((d)[0]), "+f"((d)[1]), "+f"((d)[2]), "+f"((d)[3]) \
        : "r"((a)[0]), "r"((a)[1]), "r"((a)[2]), "r"((a)[3]), \
          "r"((b)[0]), "r"((b)[1]))
#define CP16(dst, src) \
    asm volatile("cp.async.cg.shared.global [%0], [%1], 16;" :: "r"(dst), "l"(src))
#define CP_COMMIT() asm volatile("cp.async.commit_group;" ::: "memory")
#define CP_WAIT2()  asm volatile("cp.async.wait_group 2;" ::: "memory")
#define CP_WAIT1()  asm volatile("cp.async.wait_group 1;" ::: "memory")
#define CP_WAIT0()  asm volatile("cp.async.wait_group 0;" ::: "memory")

// pack two fp32 -> fp16x2 hi word + fp16x2 residual-lo word
__device__ __forceinline__ void split2h(float a, float b, uint32_t &h, uint32_t &l) {
    hf ha = __float2half_rn(a), hb = __float2half_rn(b);
    float ra = a - __half2float(ha);
    float rb = b - __half2float(hb);
    hf la = __float2half_rn(ra), lb = __float2half_rn(rb);
    h = (uint32_t)__half_as_ushort(ha) | ((uint32_t)__half_as_ushort(hb) << 16);
    l = (uint32_t)__half_as_ushort(la) | ((uint32_t)__half_as_ushort(lb) << 16);
}
__device__ __forceinline__ uint32_t pack2h(float a, float b) {
    __half2 p = __floats2half2_rn(a, b);
    return *(uint32_t*)&p;
}

// ---------------- scratch (device globals) -----------------------------------
__device__ float g_h  [MM*DD];        // residual stream
__device__ hf    g_xh [MM*DD];        // activation hi (LN out / attn out)
__device__ hf    g_xl [MM*DD];
__device__ hf    g_mh [MM*DMM];       // mlp hidden (fp16)
__device__ hf    g_qh [MM*DD];        // attention Q hi/lo, K, V (fp16)
__device__ hf    g_ql [MM*DD];
__device__ hf    g_kb [MM*DD];
__device__ hf    g_vb [MM*DD];

// transposed fp16 weights [N,K]
#define W_QKV0 0
#define W_OUT0 3145728
#define W_W10  4194304
#define W_W20  8388608
#define W_HEAD 12582912
#define WTOT   28966912
__device__ hf g_w[WTOT];

// ---------------- embedding --------------------------------------------------
__global__ void embed_kernel(const int* __restrict__ x,
                             const float* __restrict__ tok,
                             const float* __restrict__ pos,
                             float* __restrict__ h)
{
    int i = blockIdx.x * blockDim.x + threadIdx.x;
    int d  = i & (DD-1);
    int bl = i / DD;
    int l  = bl & (LL-1);
    h[i] = tok[(size_t)x[bl]*DD + d] + pos[l*DD + d];
}

// ---------------- layernorm (writes fp16 hi/lo split directly) ---------------
__global__ __launch_bounds__(256) void layernorm_kernel(
    const float* __restrict__ x, const float* __restrict__ g,
    const float* __restrict__ b, hf* __restrict__ yh, hf* __restrict__ yl)
{
    __shared__ float red[16];
    __shared__ float stats[2];
    int row = blockIdx.x;
    int tid = threadIdx.x;
    const float2* xr = (const float2*)(x + (size_t)row*DD);
    float2 v = xr[tid];
    float s = v.x + v.y;
    float q = v.x*v.x + v.y*v.y;
    #pragma unroll
    for (int o = 16; o; o >>= 1) {
        s += __shfl_down_sync(0xffffffffu, s, o);
        q += __shfl_down_sync(0xffffffffu, q, o);
    }
    int w = tid >> 5;
    if ((tid & 31) == 0) { red[w] = s; red[w+8] = q; }
    __syncthreads();
    if (tid < 32) {
        s = (tid < 8) ? red[tid]   : 0.f;
        q = (tid < 8) ? red[tid+8] : 0.f;
        #pragma unroll
        for (int o = 4; o; o >>= 1) {
            s += __shfl_down_sync(0xffffffffu, s, o);
            q += __shfl_down_sync(0xffffffffu, q, o);
        }
        if (tid == 0) {
            float mu  = s * (1.0f/DD);
            float var = q * (1.0f/DD) - mu*mu;
            stats[0] = mu;
            stats[1] = rsqrtf(var + 1e-5f);
        }
    }
    __syncthreads();
    float mu = stats[0], inv = stats[1];
    float2 gg = ((const float2*)g)[tid];
    float2 bb = ((const float2*)b)[tid];
    float ox = (v.x - mu)*inv*gg.x + bb.x;
    float oy = (v.y - mu)*inv*gg.y + bb.y;
    uint32_t hh, ll;
    split2h(ox, oy, hh, ll);
    *(uint32_t*)(yh + (size_t)row*DD + 2*tid) = hh;
    *(uint32_t*)(yl + (size_t)row*DD + 2*tid) = ll;
}

// ---------------- weight transpose+convert: [K,N] -> [N,K] fp16 --------------
__global__ __launch_bounds__(256) void tconv_kernel(
    const float* __restrict__ in, hf* __restrict__ w, int K, int N)
{
    __shared__ float t[32][33];
    int n0 = blockIdx.x * 32, k0 = blockIdx.y * 32;
    int tx = threadIdx.x, ty = threadIdx.y;
    #pragma unroll
    for (int i = ty; i < 32; i += 8)
        t[i][tx] = in[(size_t)(k0+i)*N + n0 + tx];
    __syncthreads();
    #pragma unroll
    for (int i = ty; i < 32; i += 8)
        w[(size_t)(n0+i)*K + k0 + tx] = __float2half_rn(t[tx][i]);
}

// ---------------- fp16 GEMM, cp.async 3-stage, NPASS A passes ----------------
// 256 threads, CTA tile 128 x BN. BN=256: warp 64x64; BN=128: warp 32x64.
// NPASS=1: C = Ah @ B^T. NPASS=2: C = (Ah+Al) @ B^T.
// fuse: 0=+bias->f32, 1=gelu(+bias)->fp16 (Ch only), 2=+bias+res->f32,
//       3=plain->f32, 4=+bias-> split qkv: Q fp16 hi/lo, K/V fp16 (stride DD)
#define TSTR 72   // smem row stride in fp16 elems (144B: conflict-free ldmatrix)

template<int BN, int NPASS>
__global__ __launch_bounds__(256) void tcgemm(
    const hf* __restrict__ Ahp, const hf* __restrict__ Alp,
    const hf* __restrict__ Bp,
    const float* __restrict__ bias, const float* __restrict__ res,
    float* __restrict__ C, hf* __restrict__ Ch, hf* __restrict__ Cl,
    hf* __restrict__ Kb, hf* __restrict__ Vb,
    int Kd, int Nd, int fuse)
{
    constexpr int NWN = BN/64;          // warps in N dir (4 or 2)
    constexpr int NWM = 8/NWN;          // warps in M dir (2 or 4)
    constexpr int WMT = (128/NWM)/16;   // m16 tiles per warp (4 or 2)
    constexpr int AE = 128*TSTR;
    constexpr int BE = BN*TSTR;
    constexpr int STAGE = NPASS*AE + BE;

    extern __shared__ hf sm[];
    uint32_t smb = smem_u32(sm);

    int tid = threadIdx.x, lane = tid & 31, wid = tid >> 5;
    int m0w = (wid / NWN) * (WMT*16);
    int n0w = (wid % NWN) * 64;
    int bn0  = blockIdx.x * BN;
    int row0 = blockIdx.y * 128;

    float acc[WMT][8][4];
    #pragma unroll
    for (int i = 0; i < WMT; i++)
        #pragma unroll
        for (int j = 0; j < 8; j++)
            #pragma unroll
            for (int k = 0; k < 4; k++) acc[i][j][k] = 0.f;

    int kseg = Kd >> 6;

    auto load_stage = [&](int buf, int kk) {
        uint32_t sb = smb + buf*STAGE*2;
        #pragma unroll
        for (int p = 0; p < 4; p++) {
            int id = tid + (p<<8); int r = id>>3, cc = (id&7)<<3;
            CP16(sb + (r*TSTR + cc)*2,
                 Ahp + (size_t)(row0+r)*Kd + kk + cc);
        }
        if (NPASS == 2) {
            #pragma unroll
            for (int p = 0; p < 4; p++) {
                int id = tid + (p<<8); int r = id>>3, cc = (id&7)<<3;
                CP16(sb + (AE + r*TSTR + cc)*2,
                     Alp + (size_t)(row0+r)*Kd + kk + cc);
            }
        }
        #pragma unroll
        for (int p = 0; p < BN/32; p++) {
            int id = tid + (p<<8); int r = id>>3, cc = (id&7)<<3;
            CP16(sb + (NPASS*AE + r*TSTR + cc)*2,
                 Bp + (size_t)(bn0+r)*Kd + kk + cc);
        }
    };

    load_stage(0, 0);
    CP_COMMIT();
    load_stage(1, 64);
    CP_COMMIT();

    for (int c = 0; c < kseg; c++) {
        if (c + 2 < kseg) {
            load_stage((c+2)%3, (c+2)<<6);
            CP_COMMIT();
            CP_WAIT2();
        } else if (c + 1 < kseg) {
            CP_WAIT1();
        } else {
            CP_WAIT0();
        }
        __syncthreads();

        uint32_t ab  = smb + (c%3)*STAGE*2;
        uint32_t alb = ab + AE*2;
        uint32_t bbb = ab + NPASS*AE*2;

        #pragma unroll
        for (int ks = 0; ks < 4; ks++) {
            uint32_t ah4[WMT][4], al4[WMT][4];
            int aoff = ((m0w + (lane & 15))*TSTR + ks*16 + ((lane >> 4) << 3)) * 2;
            #pragma unroll
            for (int mt = 0; mt < WMT; mt++) {
                LDSM_X4(ah4[mt][0],ah4[mt][1],ah4[mt][2],ah4[mt][3],
                        ab  + aoff + mt*16*TSTR*2);
                if (NPASS == 2) {
                    LDSM_X4(al4[mt][0],al4[mt][1],al4[mt][2],al4[mt][3],
                            alb + aoff + mt*16*TSTR*2);
                }
            }
            int boff = ((n0w + ((lane >> 4) << 3) + (lane & 7))*TSTR +
                        ks*16 + (((lane >> 3) & 1) << 3)) * 2;
            #pragma unroll
            for (int nt2 = 0; nt2 < 4; nt2++) {
                uint32_t b4[4];
                LDSM_X4(b4[0],b4[1],b4[2],b4[3], bbb + boff + nt2*16*TSTR*2);
                uint32_t b01[2]={b4[0],b4[1]}, b23[2]={b4[2],b4[3]};
                #pragma unroll
                for (int mt = 0; mt < WMT; mt++) {
                    MMA16816(acc[mt][2*nt2],   ah4[mt], b01);
                    MMA16816(acc[mt][2*nt2+1], ah4[mt], b23);
                }
                if (NPASS == 2) {
                    #pragma unroll
                    for (int mt = 0; mt < WMT; mt++) {
                        MMA16816(acc[mt][2*nt2],   al4[mt], b01);
                        MMA16816(acc[mt][2*nt2+1], al4[mt], b23);
                    }
                }
            }
        }
        __syncthreads();
    }

    // epilogue
    #pragma unroll
    for (int mt = 0; mt < WMT; mt++) {
        int r0 = row0 + m0w + mt*16 + (lane >> 2);
        #pragma unroll
        for (int nt = 0; nt < 8; nt++) {
            int col = bn0 + n0w + nt*8 + ((lane & 3) << 1);
            float2 v0 = make_float2(acc[mt][nt][0], acc[mt][nt][1]);
            float2 v1 = make_float2(acc[mt][nt][2], acc[mt][nt][3]);
            if (fuse != 3) {
                float2 bv = *(const float2*)(bias + col);
                v0.x += bv.x; v0.y += bv.y;
                v1.x += bv.x; v1.y += bv.y;
            }
            if (fuse == 4) {
                if (col < DD) {
                    uint32_t h0, l0, h1, l1;
                    split2h(v0.x, v0.y, h0, l0);
                    split2h(v1.x, v1.y, h1, l1);
                    *(uint32_t*)(Ch + (size_t)r0*DD + col)     = h0;
                    *(uint32_t*)(Cl + (size_t)r0*DD + col)     = l0;
                    *(uint32_t*)(Ch + (size_t)(r0+8)*DD + col) = h1;
                    *(uint32_t*)(Cl + (size_t)(r0+8)*DD + col) = l1;
                } else if (col < 2*DD) {
                    *(uint32_t*)(Kb + (size_t)r0*DD + col - DD)     = pack2h(v0.x, v0.y);
                    *(uint32_t*)(Kb + (size_t)(r0+8)*DD + col - DD) = pack2h(v1.x, v1.y);
                } else {
                    *(uint32_t*)(Vb + (size_t)r0*DD + col - 2*DD)     = pack2h(v0.x, v0.y);
                    *(uint32_t*)(Vb + (size_t)(r0+8)*DD + col - 2*DD) = pack2h(v1.x, v1.y);
                }
                continue;
            }
            if (fuse == 1) {
                v0.x = 0.5f*v0.x*(1.0f + erff(v0.x*0.7071067811865475f));
                v0.y = 0.5f*v0.y*(1.0f + erff(v0.y*0.7071067811865475f));
                v1.x = 0.5f*v1.x*(1.0f + erff(v1.x*0.7071067811865475f));
                v1.y = 0.5f*v1.y*(1.0f + erff(v1.y*0.7071067811865475f));
                *(uint32_t*)(Ch + (size_t)r0*Nd + col)     = pack2h(v0.x, v0.y);
                *(uint32_t*)(Ch + (size_t)(r0+8)*Nd + col) = pack2h(v1.x, v1.y);
                continue;
            }
            if (fuse == 2) {
                float2 r0v = *(const float2*)(res + (size_t)r0*Nd + col);
                float2 r1v = *(const float2*)(res + (size_t)(r0+8)*Nd + col);
                v0.x += r0v.x; v0.y += r0v.y;
                v1.x += r1v.x; v1.y += r1v.y;
            }
            *(float2*)(C + (size_t)r0*Nd + col)     = v0;
            *(float2*)(C + (size_t)(r0+8)*Nd + col) = v1;
        }
    }
}

#define GS256_1 165888
#define GS128_1 110592
#define GS256_2 221184

// ---------------- tensor-core flash attention (fp16 inputs) ------------------
// S = Qh K + Ql K; PV single pass. K/V tiles double-buffered via cp.async.
#define ATQ 128
#define ATK 64
#define SQH 0
#define SQL 9216
#define SK0 18432
#define ATTN_SMEM (36864*2)

__global__ __launch_bounds__(256, 2) void attn_kernel(
    const hf* __restrict__ qh, const hf* __restrict__ ql,
    const hf* __restrict__ kb, const hf* __restrict__ vb,
    hf* __restrict__ oh)
{
    extern __shared__ hf smatt[];
    hf* sm = smatt;
    uint32_t smb = smem_u32(sm);

    int q0 = blockIdx.x * ATQ;
    int hh = blockIdx.y;
    int bb = blockIdx.z;
    int bbLL = bb * LL;
    int hoff = hh * HDD;

    int tid = threadIdx.x, lane = tid & 31, wid = tid >> 5;
    int wrow0 = q0 + wid*16;

    // load Q tile (128x64 fp16 hi/lo)
    #pragma unroll
    for (int p = 0; p < 4; p++) {
        int id = tid + (p << 8);
        int r  = id >> 3;
        int c8 = (id & 7) << 3;
        size_t g = (size_t)(bbLL + q0 + r)*DD + hoff + c8;
        *(uint4*)(sm + SQH + r*TSTR + c8) = *(const uint4*)(qh + g);
        *(uint4*)(sm + SQL + r*TSTR + c8) = *(const uint4*)(ql + g);
    }

    auto load_kv = [&](int t, int buf) {
        int k0 = t * ATK;
        uint32_t sk = smb + (SK0 + buf*9216)*2;
        uint32_t sv = sk + 4608*2;
        #pragma unroll
        for (int p = 0; p < 2; p++) {
            int id = tid + (p << 8);
            int r  = id >> 3;
            int c8 = (id & 7) << 3;
            size_t g = (size_t)(bbLL + k0 + r)*DD + hoff + c8;
            CP16(sk + (r*TSTR + c8)*2, kb + g);
            CP16(sv + (r*TSTR + c8)*2, vb + g);
        }
    };

    float Oa[8][4];
    #pragma unroll
    for (int i = 0; i < 8; i++)
        #pragma unroll
        for (int j = 0; j < 4; j++) Oa[i][j] = 0.f;
    float m0 = -1e30f, m1 = -1e30f, l0s = 0.f, l1s = 0.f;

    int qfb = ((wid*16 + (lane & 15))*TSTR + ((lane >> 4) << 3)) * 2;
    int krow = ((lane >> 4) << 3) + (lane & 7);
    int kcol = (((lane >> 3) & 1) << 3);
    int vrow = (((lane >> 3) & 1) << 3) + (lane & 7);
    int vcol = ((lane >> 4) << 3);
    int mr   = lane >> 2;
    int mc2  = (lane & 3) << 1;

    int ntiles = (q0 + ATQ) / ATK;
    load_kv(0, 0);
    CP_COMMIT();

    for (int t = 0; t < ntiles; t++) {
        int k0 = t * ATK;
        if (t + 1 < ntiles) {
            load_kv(t+1, (t+1) & 1);
            CP_COMMIT();
            CP_WAIT1();
        } else {
            CP_WAIT0();
        }
        __syncthreads();

        if (k0 <= wrow0 + 15) {
            uint32_t skb = smb + (SK0 + (t&1)*9216)*2;
            uint32_t svb = skb + 4608*2;

            // ---- S = Qh K + Ql K ----
            float Sa[8][4];
            #pragma unroll
            for (int i = 0; i < 8; i++)
                #pragma unroll
                for (int j = 0; j < 4; j++) Sa[i][j] = 0.f;

            #pragma unroll
            for (int ks = 0; ks < 4; ks++) {
                uint32_t qhf[4], qlf[4];
                LDSM_X4(qhf[0],qhf[1],qhf[2],qhf[3], smb + SQH*2 + qfb + ks*32);
                LDSM_X4(qlf[0],qlf[1],qlf[2],qlf[3], smb + SQL*2 + qfb + ks*32);
                #pragma unroll
                for (int np = 0; np < 4; np++) {
                    uint32_t kf[4];
                    LDSM_X4(kf[0],kf[1],kf[2],kf[3],
                            skb + ((np*16 + krow)*TSTR + kcol)*2 + ks*32);
                    uint32_t b01[2] = {kf[0],kf[1]}, b23[2] = {kf[2],kf[3]};
                    MMA16816(Sa[2*np],   qhf, b01);
                    MMA16816(Sa[2*np+1], qhf, b23);
                    MMA16816(Sa[2*np],   qlf, b01);
                    MMA16816(Sa[2*np+1], qlf, b23);
                }
            }

            // scale + causal mask
            #pragma unroll
            for (int nt = 0; nt < 8; nt++)
                #pragma unroll
                for (int j = 0; j < 4; j++) Sa[nt][j] *= 0.125f;
            if (k0 + 63 > wrow0) {
                int r0g = wrow0 + mr, r1g = r0g + 8;
                #pragma unroll
                for (int nt = 0; nt < 8; nt++) {
                    int col = k0 + nt*8 + mc2;
                    if (col   > r0g) Sa[nt][0] = -1e30f;
                    if (col+1 > r0g) Sa[nt][1] = -1e30f;
                    if (col   > r1g) Sa[nt][2] = -1e30f;
                    if (col+1 > r1g) Sa[nt][3] = -1e30f;
                }
            }

            // ---- online softmax in registers ----
            float rx0 = -1e30f, rx1 = -1e30f;
            #pragma unroll
            for (int nt = 0; nt < 8; nt++) {
                rx0 = fmaxf(rx0, fmaxf(Sa[nt][0], Sa[nt][1]));
                rx1 = fmaxf(rx1, fmaxf(Sa[nt][2], Sa[nt][3]));
            }
            rx0 = fmaxf(rx0, __shfl_xor_sync(0xffffffffu, rx0, 1));
            rx0 = fmaxf(rx0, __shfl_xor_sync(0xffffffffu, rx0, 2));
            rx1 = fmaxf(rx1, __shfl_xor_sync(0xffffffffu, rx1, 1));
            rx1 = fmaxf(rx1, __shfl_xor_sync(0xffffffffu, rx1, 2));
            float mn0 = fmaxf(m0, rx0), mn1 = fmaxf(m1, rx1);
            float a0 = __expf(m0 - mn0), a1 = __expf(m1 - mn1);
            float s0 = 0.f, s1 = 0.f;
            #pragma unroll
            for (int nt = 0; nt < 8; nt++) {
                Sa[nt][0] = __expf(Sa[nt][0] - mn0);
                Sa[nt][1] = __expf(Sa[nt][1] - mn0);
                Sa[nt][2] = __expf(Sa[nt][2] - mn1);
                Sa[nt][3] = __expf(Sa[nt][3] - mn1);
                s0 += Sa[nt][0] + Sa[nt][1];
                s1 += Sa[nt][2] + Sa[nt][3];
            }
            s0 += __shfl_xor_sync(0xffffffffu, s0, 1);
            s0 += __shfl_xor_sync(0xffffffffu, s0, 2);
            s1 += __shfl_xor_sync(0xffffffffu, s1, 1);
            s1 += __shfl_xor_sync(0xffffffffu, s1, 2);
            l0s = l0s*a0 + s0;  l1s = l1s*a1 + s1;
            m0 = mn0; m1 = mn1;
            #pragma unroll
            for (int nt = 0; nt < 8; nt++) {
                Oa[nt][0] *= a0; Oa[nt][1] *= a0;
                Oa[nt][2] *= a1; Oa[nt][3] *= a1;
            }

            // ---- O += P V ----
            #pragma unroll
            for (int ks = 0; ks < 4; ks++) {
                uint32_t ph[4];
                ph[0] = pack2h(Sa[2*ks][0],   Sa[2*ks][1]);
                ph[1] = pack2h(Sa[2*ks][2],   Sa[2*ks][3]);
                ph[2] = pack2h(Sa[2*ks+1][0], Sa[2*ks+1][1]);
                ph[3] = pack2h(Sa[2*ks+1][2], Sa[2*ks+1][3]);
                #pragma unroll
                for (int np = 0; np < 4; np++) {
                    uint32_t vf[4];
                    LDSM_X4_T(vf[0],vf[1],vf[2],vf[3],
                              svb + ((ks*16 + vrow)*TSTR + np*16 + vcol)*2);
                    uint32_t b01[2] = {vf[0],vf[1]}, b23[2] = {vf[2],vf[3]};
                    MMA16816(Oa[2*np],   ph, b01);
                    MMA16816(Oa[2*np+1], ph, b23);
                }
            }
        }
        __syncthreads();
    }

    // ---- write output (fp16 hi only; out-proj is single-pass) ----
    float inv0 = 1.0f / l0s, inv1 = 1.0f / l1s;
    size_t r0g = (size_t)bbLL + wrow0 + mr;
    size_t r1g = r0g + 8;
    int cb = hoff + mc2;
    #pragma unroll
    for (int nt = 0; nt < 8; nt++) {
        int col = cb + nt*8;
        *(uint32_t*)(oh + r0g*DD + col) = pack2h(Oa[nt][0]*inv0, Oa[nt][1]*inv0);
        *(uint32_t*)(oh + r1g*DD + col) = pack2h(Oa[nt][2]*inv1, Oa[nt][3]*inv1);
    }
}

// ---------------- launcher ----------------------------------------------------
extern "C" void kernel_launch(void* const* d_in, const int* in_sizes, int n_in,
                              void* d_out, int out_size)
{
    const int*   x     = (const int*)  d_in[0];
    const float* tok   = (const float*)d_in[1];
    const float* pos   = (const float*)d_in[2];
    const float* ln1g  = (const float*)d_in[3];
    const float* ln1b  = (const float*)d_in[4];
    const float* qkvw  = (const float*)d_in[5];
    const float* qkvb  = (const float*)d_in[6];
    const float* outw  = (const float*)d_in[7];
    const float* outb  = (const float*)d_in[8];
    const float* ln2g  = (const float*)d_in[9];
    const float* ln2b  = (const float*)d_in[10];
    const float* w1    = (const float*)d_in[11];
    const float* b1    = (const float*)d_in[12];
    const float* w2    = (const float*)d_in[13];
    const float* b2    = (const float*)d_in[14];
    const float* lnfg  = (const float*)d_in[15];
    const float* lnfb  = (const float*)d_in[16];
    const float* headw = (const float*)d_in[17];
    float* out = (float*)d_out;

    float *h;
    hf *xh, *xl, *mh, *w, *qh, *ql, *kb, *vb;
    cudaGetSymbolAddress((void**)&h,   g_h);
    cudaGetSymbolAddress((void**)&xh,  g_xh);
    cudaGetSymbolAddress((void**)&xl,  g_xl);
    cudaGetSymbolAddress((void**)&mh,  g_mh);
    cudaGetSymbolAddress((void**)&w,   g_w);
    cudaGetSymbolAddress((void**)&qh,  g_qh);
    cudaGetSymbolAddress((void**)&ql,  g_ql);
    cudaGetSymbolAddress((void**)&kb,  g_kb);
    cudaGetSymbolAddress((void**)&vb,  g_vb);

    cudaFuncSetAttribute(attn_kernel,
        cudaFuncAttributeMaxDynamicSharedMemorySize, ATTN_SMEM);
    cudaFuncSetAttribute(tcgemm<256,1>,
        cudaFuncAttributeMaxDynamicSharedMemorySize, GS256_1);
    cudaFuncSetAttribute(tcgemm<128,1>,
        cudaFuncAttributeMaxDynamicSharedMemorySize, GS128_1);
    cudaFuncSetAttribute(tcgemm<256,2>,
        cudaFuncAttributeMaxDynamicSharedMemorySize, GS256_2);

    // weight prep: transpose [K,N] -> [N,K] + fp16 convert
    dim3 tb(32, 8);
    for (int i = 0; i < NLL; i++) {
        tconv_kernel<<<dim3(1536/32, 512/32), tb>>>(
            qkvw + (size_t)i*DD*3*DD, w + W_QKV0 + (size_t)i*786432, 512, 1536);
        tconv_kernel<<<dim3(512/32, 512/32), tb>>>(
            outw + (size_t)i*DD*DD, w + W_OUT0 + (size_t)i*262144, 512, 512);
        tconv_kernel<<<dim3(2048/32, 512/32), tb>>>(
            w1 + (size_t)i*DD*DMM, w + W_W10 + (size_t)i*1048576, 512, 2048);
        tconv_kernel<<<dim3(512/32, 2048/32), tb>>>(
            w2 + (size_t)i*DMM*DD, w + W_W20 + (size_t)i*1048576, 2048, 512);
    }
    tconv_kernel<<<dim3(32000/32, 512/32), tb>>>(
        headw, w + W_HEAD, 512, 32000);

    embed_kernel<<<(MM*DD)/256, 256>>>(x, tok, pos, h);

    for (int i = 0; i < NLL; i++) {
        // attn block
        layernorm_kernel<<<MM, 256>>>(h, ln1g + i*DD, ln1b + i*DD, xh, xl);
        tcgemm<256,1><<<dim3(1536/256, MM/128), 256, GS256_1>>>(
            xh, xl, w + W_QKV0 + (size_t)i*786432,
            qkvb + (size_t)i*3*DD, nullptr, nullptr, qh, ql, kb, vb,
            512, 1536, 4);
        attn_kernel<<<dim3(LL/ATQ, NHH, BB), 256, ATTN_SMEM>>>(
            qh, ql, kb, vb, xh);
        tcgemm<128,1><<<dim3(512/128, MM/128), 256, GS128_1>>>(
            xh, nullptr, w + W_OUT0 + (size_t)i*262144,
            outb + (size_t)i*DD, h, h, nullptr, nullptr, nullptr, nullptr,
            512, 512, 2);
        // mlp block
        layernorm_kernel<<<MM, 256>>>(h, ln2g + i*DD, ln2b + i*DD, xh, xl);
        tcgemm<256,1><<<dim3(2048/256, MM/128), 256, GS256_1>>>(
            xh, nullptr, w + W_W10 + (size_t)i*1048576,
            b1 + (size_t)i*DMM, nullptr, nullptr, mh, nullptr, nullptr, nullptr,
            512, 2048, 1);
        tcgemm<128,1><<<dim3(512/128, MM/128), 256, GS128_1>>>(
            mh, nullptr, w + W_W20 + (size_t)i*1048576,
            b2 + (size_t)i*DD, h, h, nullptr, nullptr, nullptr, nullptr,
            2048, 512, 2);
    }

    layernorm_kernel<<<MM, 256>>>(h, lnfg, lnfb, xh, xl);
    tcgemm<256,2><<<dim3(VV/256, MM/128), 256, GS256_2>>>(
        xh, xl, w + W_HEAD,
        nullptr, nullptr, out, nullptr, nullptr, nullptr, nullptr,
        512, VV, 3);
}

// round 15
// speedup vs baseline: 1.4428x; 1.2164x over previous
#include <cuda_runtime.h>
#include <cuda_fp16.h>
#include <math.h>
#include <stdint.h>

typedef __half hf;

// Problem dims
#define BB 2
#define LL 2048
#define DD 512
#define NHH 8
#define NLL 4
#define DMM 2048
#define VV 32000
#define HDD 64
#define MM (BB*LL)          // 4096 rows

// ---------------- PTX helpers ------------------------------------------------
__device__ __forceinline__ uint32_t smem_u32(const void* p) {
    uint32_t a;
    asm("{ .reg .u64 t; cvta.to.shared.u64 t, %1; cvt.u32.u64 %0, t; }"
        : "=r"(a) : "l"(p));
    return a;
}

#define LDSM_X4(r0,r1,r2,r3,addr) \
    asm volatile("ldmatrix.sync.aligned.m8n8.x4.shared.b16 {%0,%1,%2,%3}, [%4];" \
        : "=r"(r0), "=r"(r1), "=r"(r2), "=r"(r3) : "r"(addr))
#define LDSM_X4_T(r0,r1,r2,r3,addr) \
    asm volatile("ldmatrix.sync.aligned.m8n8.x4.trans.shared.b16 {%0,%1,%2,%3}, [%4];" \
        : "=r"(r0), "=r"(r1), "=r"(r2), "=r"(r3) : "r"(addr))
#define MMA16816(d, a, b) \
    asm volatile("mma.sync.aligned.m16n8k16.row.col.f32.f16.f16.f32 " \
        "{%0,%1,%2,%3}, {%4,%5,%6,%7}, {%8,%9}, {%0,%1,%2,%3};" \
        : "+f"((d)[0]), "+f"((d)[1]), "+f"((d)[2]), "+f"((d)[3]) \
        : "r"((a)[0]), "r"((a)[1]), "r"((a)[2]), "r"((a)[3]), \
          "r"((b)[0]), "r"((b)[1]))
#define CP16(dst, src) \
    asm volatile("cp.async.cg.shared.global [%0], [%1], 16;" :: "r"(dst), "l"(src))
#define CP_COMMIT() asm volatile("cp.async.commit_group;" ::: "memory")
#define CP_WAIT0()  asm volatile("cp.async.wait_group 0;" ::: "memory")

// pack two fp32 -> fp16x2 hi word + fp16x2 residual-lo word
__device__ __forceinline__ void split2h(float a, float b, uint32_t &h, uint32_t &l) {
    hf ha = __float2half_rn(a), hb = __float2half_rn(b);
    float ra = a - __half2float(ha);
    float rb = b - __half2float(hb);
    hf la = __float2half_rn(ra), lb = __float2half_rn(rb);
    h = (uint32_t)__half_as_ushort(ha) | ((uint32_t)__half_as_ushort(hb) << 16);
    l = (uint32_t)__half_as_ushort(la) | ((uint32_t)__half_as_ushort(lb) << 16);
}
__device__ __forceinline__ uint32_t pack2h(float a, float b) {
    __half2 p = __floats2half2_rn(a, b);
    return *(uint32_t*)&p;
}

// ---------------- scratch (device globals) -----------------------------------
__device__ float g_h  [MM*DD];        // residual stream
__device__ hf    g_xh [MM*DD];        // activation (LN out / attn out)
__device__ hf    g_mh [MM*DMM];       // mlp hidden (fp16)
__device__ hf    g_qh [MM*DD];        // attention Q hi/lo, K, V (fp16)
__device__ hf    g_ql [MM*DD];
__device__ hf    g_kb [MM*DD];
__device__ hf    g_vb [MM*DD];

// transposed fp16 weights [N,K]
#define W_QKV0 0
#define W_OUT0 3145728
#define W_W10  4194304
#define W_W20  8388608
#define W_HEAD 12582912
#define WTOT   28966912
__device__ hf g_w[WTOT];

// ---------------- embedding --------------------------------------------------
__global__ void embed_kernel(const int* __restrict__ x,
                             const float* __restrict__ tok,
                             const float* __restrict__ pos,
                             float* __restrict__ h)
{
    int i = blockIdx.x * blockDim.x + threadIdx.x;
    int d  = i & (DD-1);
    int bl = i / DD;
    int l  = bl & (LL-1);
    h[i] = tok[(size_t)x[bl]*DD + d] + pos[l*DD + d];
}

// ---------------- layernorm (fp16 hi output only) ----------------------------
__global__ __launch_bounds__(256) void layernorm_kernel(
    const float* __restrict__ x, const float* __restrict__ g,
    const float* __restrict__ b, hf* __restrict__ yh)
{
    __shared__ float red[16];
    __shared__ float stats[2];
    int row = blockIdx.x;
    int tid = threadIdx.x;
    const float2* xr = (const float2*)(x + (size_t)row*DD);
    float2 v = xr[tid];
    float s = v.x + v.y;
    float q = v.x*v.x + v.y*v.y;
    #pragma unroll
    for (int o = 16; o; o >>= 1) {
        s += __shfl_down_sync(0xffffffffu, s, o);
        q += __shfl_down_sync(0xffffffffu, q, o);
    }
    int w = tid >> 5;
    if ((tid & 31) == 0) { red[w] = s; red[w+8] = q; }
    __syncthreads();
    if (tid < 32) {
        s = (tid < 8) ? red[tid]   : 0.f;
        q = (tid < 8) ? red[tid+8] : 0.f;
        #pragma unroll
        for (int o = 4; o; o >>= 1) {
            s += __shfl_down_sync(0xffffffffu, s, o);
            q += __shfl_down_sync(0xffffffffu, q, o);
        }
        if (tid == 0) {
            float mu  = s * (1.0f/DD);
            float var = q * (1.0f/DD) - mu*mu;
            stats[0] = mu;
            stats[1] = rsqrtf(var + 1e-5f);
        }
    }
    __syncthreads();
    float mu = stats[0], inv = stats[1];
    float2 gg = ((const float2*)g)[tid];
    float2 bb = ((const float2*)b)[tid];
    float ox = (v.x - mu)*inv*gg.x + bb.x;
    float oy = (v.y - mu)*inv*gg.y + bb.y;
    *(uint32_t*)(yh + (size_t)row*DD + 2*tid) = pack2h(ox, oy);
}

// ---------------- weight transpose+convert: [K,N] -> [N,K] fp16 --------------
__global__ __launch_bounds__(256) void tconv_kernel(
    const float* __restrict__ in, hf* __restrict__ w, int K, int N)
{
    __shared__ float t[32][33];
    int n0 = blockIdx.x * 32, k0 = blockIdx.y * 32;
    int tx = threadIdx.x, ty = threadIdx.y;
    #pragma unroll
    for (int i = ty; i < 32; i += 8)
        t[i][tx] = in[(size_t)(k0+i)*N + n0 + tx];
    __syncthreads();
    #pragma unroll
    for (int i = ty; i < 32; i += 8)
        w[(size_t)(n0+i)*K + k0 + tx] = __float2half_rn(t[tx][i]);
}

// ---------------- fp16 GEMM, 2-stage cp.async, ONE sync per chunk ------------
// 256 threads, CTA tile 128 x BN. BN=256: warp 64x64 (1 CTA/SM);
// BN=128: warp 32x64 (2 CTAs/SM).
// fuse: 0=+bias->f32, 1=gelu(+bias)->fp16, 2=+bias+res->f32, 3=plain->f32,
//       4=+bias-> split qkv: Q fp16 hi/lo, K/V fp16 (stride DD)
#define TSTR 72   // smem row stride in fp16 elems (144B: conflict-free ldmatrix)

template<int BN>
__global__ __launch_bounds__(256, BN == 128 ? 2 : 1) void tcgemm(
    const hf* __restrict__ Ahp,
    const hf* __restrict__ Bp,
    const float* __restrict__ bias, const float* __restrict__ res,
    float* __restrict__ C, hf* __restrict__ Ch, hf* __restrict__ Cl,
    hf* __restrict__ Kb, hf* __restrict__ Vb,
    int Kd, int Nd, int fuse)
{
    constexpr int NWN = BN/64;          // warps in N dir (4 or 2)
    constexpr int NWM = 8/NWN;          // warps in M dir (2 or 4)
    constexpr int WMT = (128/NWM)/16;   // m16 tiles per warp (4 or 2)
    constexpr int AE = 128*TSTR;
    constexpr int BE = BN*TSTR;
    constexpr int STAGE = AE + BE;      // elems per stage

    extern __shared__ hf sm[];
    uint32_t smb = smem_u32(sm);

    int tid = threadIdx.x, lane = tid & 31, wid = tid >> 5;
    int m0w = (wid / NWN) * (WMT*16);
    int n0w = (wid % NWN) * 64;
    int bn0  = blockIdx.x * BN;
    int row0 = blockIdx.y * 128;

    float acc[WMT][8][4];
    #pragma unroll
    for (int i = 0; i < WMT; i++)
        #pragma unroll
        for (int j = 0; j < 8; j++)
            #pragma unroll
            for (int k = 0; k < 4; k++) acc[i][j][k] = 0.f;

    int kseg = Kd >> 6;

    auto load_stage = [&](int buf, int kk) {
        uint32_t sb = smb + buf*STAGE*2;
        #pragma unroll
        for (int p = 0; p < 4; p++) {
            int id = tid + (p<<8); int r = id>>3, cc = (id&7)<<3;
            CP16(sb + (r*TSTR + cc)*2,
                 Ahp + (size_t)(row0+r)*Kd + kk + cc);
        }
        #pragma unroll
        for (int p = 0; p < BN/32; p++) {
            int id = tid + (p<<8); int r = id>>3, cc = (id&7)<<3;
            CP16(sb + (AE + r*TSTR + cc)*2,
                 Bp + (size_t)(bn0+r)*Kd + kk + cc);
        }
    };

    load_stage(0, 0);
    CP_COMMIT();

    for (int c = 0; c < kseg; c++) {
        CP_WAIT0();            // stage c landed
        __syncthreads();       // visible to all; prior reads of buf (c+1)&1 done
        if (c + 1 < kseg) {
            load_stage((c+1)&1, (c+1)<<6);
            CP_COMMIT();
        }

        uint32_t ab  = smb + (c&1)*STAGE*2;
        uint32_t bbb = ab + AE*2;

        #pragma unroll
        for (int ks = 0; ks < 4; ks++) {
            uint32_t ah4[WMT][4];
            int aoff = ((m0w + (lane & 15))*TSTR + ks*16 + ((lane >> 4) << 3)) * 2;
            #pragma unroll
            for (int mt = 0; mt < WMT; mt++) {
                LDSM_X4(ah4[mt][0],ah4[mt][1],ah4[mt][2],ah4[mt][3],
                        ab + aoff + mt*16*TSTR*2);
            }
            int boff = ((n0w + ((lane >> 4) << 3) + (lane & 7))*TSTR +
                        ks*16 + (((lane >> 3) & 1) << 3)) * 2;
            #pragma unroll
            for (int nt2 = 0; nt2 < 4; nt2++) {
                uint32_t b4[4];
                LDSM_X4(b4[0],b4[1],b4[2],b4[3], bbb + boff + nt2*16*TSTR*2);
                uint32_t b01[2]={b4[0],b4[1]}, b23[2]={b4[2],b4[3]};
                #pragma unroll
                for (int mt = 0; mt < WMT; mt++) {
                    MMA16816(acc[mt][2*nt2],   ah4[mt], b01);
                    MMA16816(acc[mt][2*nt2+1], ah4[mt], b23);
                }
            }
        }
    }

    // epilogue
    #pragma unroll
    for (int mt = 0; mt < WMT; mt++) {
        int r0 = row0 + m0w + mt*16 + (lane >> 2);
        #pragma unroll
        for (int nt = 0; nt < 8; nt++) {
            int col = bn0 + n0w + nt*8 + ((lane & 3) << 1);
            float2 v0 = make_float2(acc[mt][nt][0], acc[mt][nt][1]);
            float2 v1 = make_float2(acc[mt][nt][2], acc[mt][nt][3]);
            if (fuse != 3) {
                float2 bv = *(const float2*)(bias + col);
                v0.x += bv.x; v0.y += bv.y;
                v1.x += bv.x; v1.y += bv.y;
            }
            if (fuse == 4) {
                if (col < DD) {
                    uint32_t h0, l0, h1, l1;
                    split2h(v0.x, v0.y, h0, l0);
                    split2h(v1.x, v1.y, h1, l1);
                    *(uint32_t*)(Ch + (size_t)r0*DD + col)     = h0;
                    *(uint32_t*)(Cl + (size_t)r0*DD + col)     = l0;
                    *(uint32_t*)(Ch + (size_t)(r0+8)*DD + col) = h1;
                    *(uint32_t*)(Cl + (size_t)(r0+8)*DD + col) = l1;
                } else if (col < 2*DD) {
                    *(uint32_t*)(Kb + (size_t)r0*DD + col - DD)     = pack2h(v0.x, v0.y);
                    *(uint32_t*)(Kb + (size_t)(r0+8)*DD + col - DD) = pack2h(v1.x, v1.y);
                } else {
                    *(uint32_t*)(Vb + (size_t)r0*DD + col - 2*DD)     = pack2h(v0.x, v0.y);
                    *(uint32_t*)(Vb + (size_t)(r0+8)*DD + col - 2*DD) = pack2h(v1.x, v1.y);
                }
                continue;
            }
            if (fuse == 1) {
                v0.x = 0.5f*v0.x*(1.0f + erff(v0.x*0.7071067811865475f));
                v0.y = 0.5f*v0.y*(1.0f + erff(v0.y*0.7071067811865475f));
                v1.x = 0.5f*v1.x*(1.0f + erff(v1.x*0.7071067811865475f));
                v1.y = 0.5f*v1.y*(1.0f + erff(v1.y*0.7071067811865475f));
                *(uint32_t*)(Ch + (size_t)r0*Nd + col)     = pack2h(v0.x, v0.y);
                *(uint32_t*)(Ch + (size_t)(r0+8)*Nd + col) = pack2h(v1.x, v1.y);
                continue;
            }
            if (fuse == 2) {
                float2 r0v = *(const float2*)(res + (size_t)r0*Nd + col);
                float2 r1v = *(const float2*)(res + (size_t)(r0+8)*Nd + col);
                v0.x += r0v.x; v0.y += r0v.y;
                v1.x += r1v.x; v1.y += r1v.y;
            }
            *(float2*)(C + (size_t)r0*Nd + col)     = v0;
            *(float2*)(C + (size_t)(r0+8)*Nd + col) = v1;
        }
    }
}

#define GS256 110592
#define GS128 73728

// ---------------- tensor-core flash attention (fp16 inputs) ------------------
// S = Qh K + Ql K; PV single pass. K/V double-buffered, ONE sync per tile.
#define ATQ 128
#define ATK 64
#define SQH 0
#define SQL 9216
#define SK0 18432
#define ATTN_SMEM (36864*2)

__global__ __launch_bounds__(256, 2) void attn_kernel(
    const hf* __restrict__ qh, const hf* __restrict__ ql,
    const hf* __restrict__ kb, const hf* __restrict__ vb,
    hf* __restrict__ oh)
{
    extern __shared__ hf smatt[];
    hf* sm = smatt;
    uint32_t smb = smem_u32(sm);

    int q0 = blockIdx.x * ATQ;
    int hh = blockIdx.y;
    int bb = blockIdx.z;
    int bbLL = bb * LL;
    int hoff = hh * HDD;

    int tid = threadIdx.x, lane = tid & 31, wid = tid >> 5;
    int wrow0 = q0 + wid*16;

    // load Q tile (128x64 fp16 hi/lo)
    #pragma unroll
    for (int p = 0; p < 4; p++) {
        int id = tid + (p << 8);
        int r  = id >> 3;
        int c8 = (id & 7) << 3;
        size_t g = (size_t)(bbLL + q0 + r)*DD + hoff + c8;
        *(uint4*)(sm + SQH + r*TSTR + c8) = *(const uint4*)(qh + g);
        *(uint4*)(sm + SQL + r*TSTR + c8) = *(const uint4*)(ql + g);
    }

    auto load_kv = [&](int t, int buf) {
        int k0 = t * ATK;
        uint32_t sk = smb + (SK0 + buf*9216)*2;
        uint32_t sv = sk + 4608*2;
        #pragma unroll
        for (int p = 0; p < 2; p++) {
            int id = tid + (p << 8);
            int r  = id >> 3;
            int c8 = (id & 7) << 3;
            size_t g = (size_t)(bbLL + k0 + r)*DD + hoff + c8;
            CP16(sk + (r*TSTR + c8)*2, kb + g);
            CP16(sv + (r*TSTR + c8)*2, vb + g);
        }
    };

    float Oa[8][4];
    #pragma unroll
    for (int i = 0; i < 8; i++)
        #pragma unroll
        for (int j = 0; j < 4; j++) Oa[i][j] = 0.f;
    float m0 = -1e30f, m1 = -1e30f, l0s = 0.f, l1s = 0.f;

    int qfb = ((wid*16 + (lane & 15))*TSTR + ((lane >> 4) << 3)) * 2;
    int krow = ((lane >> 4) << 3) + (lane & 7);
    int kcol = (((lane >> 3) & 1) << 3);
    int vrow = (((lane >> 3) & 1) << 3) + (lane & 7);
    int vcol = ((lane >> 4) << 3);
    int mr   = lane >> 2;
    int mc2  = (lane & 3) << 1;

    int ntiles = (q0 + ATQ) / ATK;
    load_kv(0, 0);
    CP_COMMIT();

    for (int t = 0; t < ntiles; t++) {
        int k0 = t * ATK;
        CP_WAIT0();            // tile t landed (also first-iter Q visibility)
        __syncthreads();       // prior reads of buf (t+1)&1 done
        if (t + 1 < ntiles) {
            load_kv(t+1, (t+1) & 1);
            CP_COMMIT();
        }

        if (k0 <= wrow0 + 15) {
            uint32_t skb = smb + (SK0 + (t&1)*9216)*2;
            uint32_t svb = skb + 4608*2;

            // ---- S = Qh K + Ql K ----
            float Sa[8][4];
            #pragma unroll
            for (int i = 0; i < 8; i++)
                #pragma unroll
                for (int j = 0; j < 4; j++) Sa[i][j] = 0.f;

            #pragma unroll
            for (int ks = 0; ks < 4; ks++) {
                uint32_t qhf[4], qlf[4];
                LDSM_X4(qhf[0],qhf[1],qhf[2],qhf[3], smb + SQH*2 + qfb + ks*32);
                LDSM_X4(qlf[0],qlf[1],qlf[2],qlf[3], smb + SQL*2 + qfb + ks*32);
                #pragma unroll
                for (int np = 0; np < 4; np++) {
                    uint32_t kf[4];
                    LDSM_X4(kf[0],kf[1],kf[2],kf[3],
                            skb + ((np*16 + krow)*TSTR + kcol)*2 + ks*32);
                    uint32_t b01[2] = {kf[0],kf[1]}, b23[2] = {kf[2],kf[3]};
                    MMA16816(Sa[2*np],   qhf, b01);
                    MMA16816(Sa[2*np+1], qhf, b23);
                    MMA16816(Sa[2*np],   qlf, b01);
                    MMA16816(Sa[2*np+1], qlf, b23);
                }
            }

            // scale + causal mask
            #pragma unroll
            for (int nt = 0; nt < 8; nt++)
                #pragma unroll
                for (int j = 0; j < 4; j++) Sa[nt][j] *= 0.125f;
            if (k0 + 63 > wrow0) {
                int r0g = wrow0 + mr, r1g = r0g + 8;
                #pragma unroll
                for (int nt = 0; nt < 8; nt++) {
                    int col = k0 + nt*8 + mc2;
                    if (col   > r0g) Sa[nt][0] = -1e30f;
                    if (col+1 > r0g) Sa[nt][1] = -1e30f;
                    if (col   > r1g) Sa[nt][2] = -1e30f;
                    if (col+1 > r1g) Sa[nt][3] = -1e30f;
                }
            }

            // ---- online softmax in registers ----
            float rx0 = -1e30f, rx1 = -1e30f;
            #pragma unroll
            for (int nt = 0; nt < 8; nt++) {
                rx0 = fmaxf(rx0, fmaxf(Sa[nt][0], Sa[nt][1]));
                rx1 = fmaxf(rx1, fmaxf(Sa[nt][2], Sa[nt][3]));
            }
            rx0 = fmaxf(rx0, __shfl_xor_sync(0xffffffffu, rx0, 1));
            rx0 = fmaxf(rx0, __shfl_xor_sync(0xffffffffu, rx0, 2));
            rx1 = fmaxf(rx1, __shfl_xor_sync(0xffffffffu, rx1, 1));
            rx1 = fmaxf(rx1, __shfl_xor_sync(0xffffffffu, rx1, 2));
            float mn0 = fmaxf(m0, rx0), mn1 = fmaxf(m1, rx1);
            float a0 = __expf(m0 - mn0), a1 = __expf(m1 - mn1);
            float s0 = 0.f, s1 = 0.f;
            #pragma unroll
            for (int nt = 0; nt < 8; nt++) {
                Sa[nt][0] = __expf(Sa[nt][0] - mn0);
                Sa[nt][1] = __expf(Sa[nt][1] - mn0);
                Sa[nt][2] = __expf(Sa[nt][2] - mn1);
                Sa[nt][3] = __expf(Sa[nt][3] - mn1);
                s0 += Sa[nt][0] + Sa[nt][1];
                s1 += Sa[nt][2] + Sa[nt][3];
            }
            s0 += __shfl_xor_sync(0xffffffffu, s0, 1);
            s0 += __shfl_xor_sync(0xffffffffu, s0, 2);
            s1 += __shfl_xor_sync(0xffffffffu, s1, 1);
            s1 += __shfl_xor_sync(0xffffffffu, s1, 2);
            l0s = l0s*a0 + s0;  l1s = l1s*a1 + s1;
            m0 = mn0; m1 = mn1;
            #pragma unroll
            for (int nt = 0; nt < 8; nt++) {
                Oa[nt][0] *= a0; Oa[nt][1] *= a0;
                Oa[nt][2] *= a1; Oa[nt][3] *= a1;
            }

            // ---- O += P V ----
            #pragma unroll
            for (int ks = 0; ks < 4; ks++) {
                uint32_t ph[4];
                ph[0] = pack2h(Sa[2*ks][0],   Sa[2*ks][1]);
                ph[1] = pack2h(Sa[2*ks][2],   Sa[2*ks][3]);
                ph[2] = pack2h(Sa[2*ks+1][0], Sa[2*ks+1][1]);
                ph[3] = pack2h(Sa[2*ks+1][2], Sa[2*ks+1][3]);
                #pragma unroll
                for (int np = 0; np < 4; np++) {
                    uint32_t vf[4];
                    LDSM_X4_T(vf[0],vf[1],vf[2],vf[3],
                              svb + ((ks*16 + vrow)*TSTR + np*16 + vcol)*2);
                    uint32_t b01[2] = {vf[0],vf[1]}, b23[2] = {vf[2],vf[3]};
                    MMA16816(Oa[2*np],   ph, b01);
                    MMA16816(Oa[2*np+1], ph, b23);
                }
            }
        }
    }

    // ---- write output (fp16; out-proj is single-pass) ----
    float inv0 = 1.0f / l0s, inv1 = 1.0f / l1s;
    size_t r0g = (size_t)bbLL + wrow0 + mr;
    size_t r1g = r0g + 8;
    int cb = hoff + mc2;
    #pragma unroll
    for (int nt = 0; nt < 8; nt++) {
        int col = cb + nt*8;
        *(uint32_t*)(oh + r0g*DD + col) = pack2h(Oa[nt][0]*inv0, Oa[nt][1]*inv0);
        *(uint32_t*)(oh + r1g*DD + col) = pack2h(Oa[nt][2]*inv1, Oa[nt][3]*inv1);
    }
}

// ---------------- launcher ----------------------------------------------------
extern "C" void kernel_launch(void* const* d_in, const int* in_sizes, int n_in,
                              void* d_out, int out_size)
{
    const int*   x     = (const int*)  d_in[0];
    const float* tok   = (const float*)d_in[1];
    const float* pos   = (const float*)d_in[2];
    const float* ln1g  = (const float*)d_in[3];
    const float* ln1b  = (const float*)d_in[4];
    const float* qkvw  = (const float*)d_in[5];
    const float* qkvb  = (const float*)d_in[6];
    const float* outw  = (const float*)d_in[7];
    const float* outb  = (const float*)d_in[8];
    const float* ln2g  = (const float*)d_in[9];
    const float* ln2b  = (const float*)d_in[10];
    const float* w1    = (const float*)d_in[11];
    const float* b1    = (const float*)d_in[12];
    const float* w2    = (const float*)d_in[13];
    const float* b2    = (const float*)d_in[14];
    const float* lnfg  = (const float*)d_in[15];
    const float* lnfb  = (const float*)d_in[16];
    const float* headw = (const float*)d_in[17];
    float* out = (float*)d_out;

    float *h;
    hf *xh, *mh, *w, *qh, *ql, *kb, *vb;
    cudaGetSymbolAddress((void**)&h,   g_h);
    cudaGetSymbolAddress((void**)&xh,  g_xh);
    cudaGetSymbolAddress((void**)&mh,  g_mh);
    cudaGetSymbolAddress((void**)&w,   g_w);
    cudaGetSymbolAddress((void**)&qh,  g_qh);
    cudaGetSymbolAddress((void**)&ql,  g_ql);
    cudaGetSymbolAddress((void**)&kb,  g_kb);
    cudaGetSymbolAddress((void**)&vb,  g_vb);

    cudaFuncSetAttribute(attn_kernel,
        cudaFuncAttributeMaxDynamicSharedMemorySize, ATTN_SMEM);
    cudaFuncSetAttribute(tcgemm<256>,
        cudaFuncAttributeMaxDynamicSharedMemorySize, GS256);
    cudaFuncSetAttribute(tcgemm<128>,
        cudaFuncAttributeMaxDynamicSharedMemorySize, GS128);

    // weight prep: transpose [K,N] -> [N,K] + fp16 convert
    dim3 tb(32, 8);
    for (int i = 0; i < NLL; i++) {
        tconv_kernel<<<dim3(1536/32, 512/32), tb>>>(
            qkvw + (size_t)i*DD*3*DD, w + W_QKV0 + (size_t)i*786432, 512, 1536);
        tconv_kernel<<<dim3(512/32, 512/32), tb>>>(
            outw + (size_t)i*DD*DD, w + W_OUT0 + (size_t)i*262144, 512, 512);
        tconv_kernel<<<dim3(2048/32, 512/32), tb>>>(
            w1 + (size_t)i*DD*DMM, w + W_W10 + (size_t)i*1048576, 512, 2048);
        tconv_kernel<<<dim3(512/32, 2048/32), tb>>>(
            w2 + (size_t)i*DMM*DD, w + W_W20 + (size_t)i*1048576, 2048, 512);
    }
    tconv_kernel<<<dim3(32000/32, 512/32), tb>>>(
        headw, w + W_HEAD, 512, 32000);

    embed_kernel<<<(MM*DD)/256, 256>>>(x, tok, pos, h);

    for (int i = 0; i < NLL; i++) {
        // attn block
        layernorm_kernel<<<MM, 256>>>(h, ln1g + i*DD, ln1b + i*DD, xh);
        tcgemm<256><<<dim3(1536/256, MM/128), 256, GS256>>>(
            xh, w + W_QKV0 + (size_t)i*786432,
            qkvb + (size_t)i*3*DD, nullptr, nullptr, qh, ql, kb, vb,
            512, 1536, 4);
        attn_kernel<<<dim3(LL/ATQ, NHH, BB), 256, ATTN_SMEM>>>(
            qh, ql, kb, vb, xh);
        tcgemm<128><<<dim3(512/128, MM/128), 256, GS128>>>(
            xh, w + W_OUT0 + (size_t)i*262144,
            outb + (size_t)i*DD, h, h, nullptr, nullptr, nullptr, nullptr,
            512, 512, 2);
        // mlp block
        layernorm_kernel<<<MM, 256>>>(h, ln2g + i*DD, ln2b + i*DD, xh);
        tcgemm<256><<<dim3(2048/256, MM/128), 256, GS256>>>(
            xh, w + W_W10 + (size_t)i*1048576,
            b1 + (size_t)i*DMM, nullptr, nullptr, mh, nullptr, nullptr, nullptr,
            512, 2048, 1);
        tcgemm<128><<<dim3(512/128, MM/128), 256, GS128>>>(
            mh, w + W_W20 + (size_t)i*1048576,
            b2 + (size_t)i*DD, h, h, nullptr, nullptr, nullptr, nullptr,
            2048, 512, 2);
    }

    layernorm_kernel<<<MM, 256>>>(h, lnfg, lnfb, xh);
    tcgemm<256><<<dim3(VV/256, MM/128), 256, GS256>>>(
        xh, w + W_HEAD,
        nullptr, nullptr, out, nullptr, nullptr, nullptr, nullptr,
        512, VV, 3);
}

// round 16
// speedup vs baseline: 1.5918x; 1.1033x over previous
#include <cuda_runtime.h>
#include <cuda_fp16.h>
#include <math.h>
#include <stdint.h>

typedef __half hf;

// Problem dims
#define BB 2
#define LL 2048
#define DD 512
#define NHH 8
#define NLL 4
#define DMM 2048
#define VV 32000
#define HDD 64
#define MM (BB*LL)          // 4096 rows

// ---------------- PTX helpers ------------------------------------------------
__device__ __forceinline__ uint32_t smem_u32(const void* p) {
    uint32_t a;
    asm("{ .reg .u64 t; cvta.to.shared.u64 t, %1; cvt.u32.u64 %0, t; }"
        : "=r"(a) : "l"(p));
    return a;
}

#define LDSM_X4(r0,r1,r2,r3,addr) \
    asm volatile("ldmatrix.sync.aligned.m8n8.x4.shared.b16 {%0,%1,%2,%3}, [%4];" \
        : "=r"(r0), "=r"(r1), "=r"(r2), "=r"(r3) : "r"(addr))
#define LDSM_X4_T(r0,r1,r2,r3,addr) \
    asm volatile("ldmatrix.sync.aligned.m8n8.x4.trans.shared.b16 {%0,%1,%2,%3}, [%4];" \
        : "=r"(r0), "=r"(r1), "=r"(r2), "=r"(r3) : "r"(addr))
#define MMA16816(d, a, b) \
    asm volatile("mma.sync.aligned.m16n8k16.row.col.f32.f16.f16.f32 " \
        "{%0,%1,%2,%3}, {%4,%5,%6,%7}, {%8,%9}, {%0,%1,%2,%3};" \
        : "+f"((d)[0]), "+f"((d)[1]), "+f"((d)[2]), "+f"((d)[3]) \
        : "r"((a)[0]), "r"((a)[1]), "r"((a)[2]), "r"((a)[3]), \
          "r"((b)[0]), "r"((b)[1]))
#define CP16(dst, src) \
    asm volatile("cp.async.cg.shared.global [%0], [%1], 16;" :: "r"(dst), "l"(src))
#define CP_COMMIT() asm volatile("cp.async.commit_group;" ::: "memory")
#define CP_WAIT0()  asm volatile("cp.async.wait_group 0;" ::: "memory")

__device__ __forceinline__ uint32_t pack2h(float a, float b) {
    __half2 p = __floats2half2_rn(a, b);
    return *(uint32_t*)&p;
}

// ---------------- scratch (device globals) -----------------------------------
__device__ float g_h  [MM*DD];        // residual stream
__device__ hf    g_xh [MM*DD];        // activation (LN out / attn out)
__device__ hf    g_mh [MM*DMM];       // mlp hidden (fp16)
__device__ hf    g_qb [MM*DD];        // attention Q, K, V (fp16)
__device__ hf    g_kb [MM*DD];
__device__ hf    g_vb [MM*DD];

// transposed fp16 weights [N,K]
#define W_QKV0 0
#define W_OUT0 3145728
#define W_W10  4194304
#define W_W20  8388608
#define W_HEAD 12582912
#define WTOT   28966912
__device__ hf g_w[WTOT];

// ---------------- embedding --------------------------------------------------
__global__ void embed_kernel(const int* __restrict__ x,
                             const float* __restrict__ tok,
                             const float* __restrict__ pos,
                             float* __restrict__ h)
{
    int i = blockIdx.x * blockDim.x + threadIdx.x;
    int d  = i & (DD-1);
    int bl = i / DD;
    int l  = bl & (LL-1);
    h[i] = tok[(size_t)x[bl]*DD + d] + pos[l*DD + d];
}

// ---------------- layernorm (fp16 output) ------------------------------------
__global__ __launch_bounds__(256) void layernorm_kernel(
    const float* __restrict__ x, const float* __restrict__ g,
    const float* __restrict__ b, hf* __restrict__ yh)
{
    __shared__ float red[16];
    __shared__ float stats[2];
    int row = blockIdx.x;
    int tid = threadIdx.x;
    const float2* xr = (const float2*)(x + (size_t)row*DD);
    float2 v = xr[tid];
    float s = v.x + v.y;
    float q = v.x*v.x + v.y*v.y;
    #pragma unroll
    for (int o = 16; o; o >>= 1) {
        s += __shfl_down_sync(0xffffffffu, s, o);
        q += __shfl_down_sync(0xffffffffu, q, o);
    }
    int w = tid >> 5;
    if ((tid & 31) == 0) { red[w] = s; red[w+8] = q; }
    __syncthreads();
    if (tid < 32) {
        s = (tid < 8) ? red[tid]   : 0.f;
        q = (tid < 8) ? red[tid+8] : 0.f;
        #pragma unroll
        for (int o = 4; o; o >>= 1) {
            s += __shfl_down_sync(0xffffffffu, s, o);
            q += __shfl_down_sync(0xffffffffu, q, o);
        }
        if (tid == 0) {
            float mu  = s * (1.0f/DD);
            float var = q * (1.0f/DD) - mu*mu;
            stats[0] = mu;
            stats[1] = rsqrtf(var + 1e-5f);
        }
    }
    __syncthreads();
    float mu = stats[0], inv = stats[1];
    float2 gg = ((const float2*)g)[tid];
    float2 bb = ((const float2*)b)[tid];
    float ox = (v.x - mu)*inv*gg.x + bb.x;
    float oy = (v.y - mu)*inv*gg.y + bb.y;
    *(uint32_t*)(yh + (size_t)row*DD + 2*tid) = pack2h(ox, oy);
}

// ------- weight transpose+convert: [K,N] -> [N,K] fp16, layer-batched --------
__global__ __launch_bounds__(256) void tconv_kernel(
    const float* __restrict__ in, hf* __restrict__ w, int K, int N,
    size_t inStride, size_t outStride)
{
    __shared__ float t[32][33];
    in += blockIdx.z * inStride;
    w  += blockIdx.z * outStride;
    int n0 = blockIdx.x * 32, k0 = blockIdx.y * 32;
    int tx = threadIdx.x, ty = threadIdx.y;
    #pragma unroll
    for (int i = ty; i < 32; i += 8)
        t[i][tx] = in[(size_t)(k0+i)*N + n0 + tx];
    __syncthreads();
    #pragma unroll
    for (int i = ty; i < 32; i += 8)
        w[(size_t)(n0+i)*K + k0 + tx] = __float2half_rn(t[tx][i]);
}

// ---------------- fp16 GEMM, 2-stage cp.async, ONE sync per chunk ------------
// 256 threads, CTA tile 128 x BN. BN=256: warp 64x64 (1 CTA/SM);
// BN=128: warp 32x64 (2 CTAs/SM).
// fuse: 0=+bias->f32, 1=gelu(+bias)->fp16, 2=+bias+res->f32, 3=plain->f32,
//       4=+bias-> split qkv: Q/K/V fp16 (stride DD)
#define TSTR 72   // smem row stride in fp16 elems (144B: conflict-free ldmatrix)

template<int BN>
__global__ __launch_bounds__(256, BN == 128 ? 2 : 1) void tcgemm(
    const hf* __restrict__ Ahp,
    const hf* __restrict__ Bp,
    const float* __restrict__ bias, const float* __restrict__ res,
    float* __restrict__ C, hf* __restrict__ Ch,
    hf* __restrict__ Kb, hf* __restrict__ Vb,
    int Kd, int Nd, int fuse)
{
    constexpr int NWN = BN/64;          // warps in N dir (4 or 2)
    constexpr int NWM = 8/NWN;          // warps in M dir (2 or 4)
    constexpr int WMT = (128/NWM)/16;   // m16 tiles per warp (4 or 2)
    constexpr int AE = 128*TSTR;
    constexpr int BE = BN*TSTR;
    constexpr int STAGE = AE + BE;      // elems per stage

    extern __shared__ hf sm[];
    uint32_t smb = smem_u32(sm);

    int tid = threadIdx.x, lane = tid & 31, wid = tid >> 5;
    int m0w = (wid / NWN) * (WMT*16);
    int n0w = (wid % NWN) * 64;
    int bn0  = blockIdx.x * BN;
    int row0 = blockIdx.y * 128;

    float acc[WMT][8][4];
    #pragma unroll
    for (int i = 0; i < WMT; i++)
        #pragma unroll
        for (int j = 0; j < 8; j++)
            #pragma unroll
            for (int k = 0; k < 4; k++) acc[i][j][k] = 0.f;

    int kseg = Kd >> 6;

    auto load_stage = [&](int buf, int kk) {
        uint32_t sb = smb + buf*STAGE*2;
        #pragma unroll
        for (int p = 0; p < 4; p++) {
            int id = tid + (p<<8); int r = id>>3, cc = (id&7)<<3;
            CP16(sb + (r*TSTR + cc)*2,
                 Ahp + (size_t)(row0+r)*Kd + kk + cc);
        }
        #pragma unroll
        for (int p = 0; p < BN/32; p++) {
            int id = tid + (p<<8); int r = id>>3, cc = (id&7)<<3;
            CP16(sb + (AE + r*TSTR + cc)*2,
                 Bp + (size_t)(bn0+r)*Kd + kk + cc);
        }
    };

    load_stage(0, 0);
    CP_COMMIT();

    for (int c = 0; c < kseg; c++) {
        CP_WAIT0();            // stage c landed
        __syncthreads();       // visible to all; prior reads of buf (c+1)&1 done
        if (c + 1 < kseg) {
            load_stage((c+1)&1, (c+1)<<6);
            CP_COMMIT();
        }

        uint32_t ab  = smb + (c&1)*STAGE*2;
        uint32_t bbb = ab + AE*2;

        #pragma unroll
        for (int ks = 0; ks < 4; ks++) {
            uint32_t ah4[WMT][4];
            int aoff = ((m0w + (lane & 15))*TSTR + ks*16 + ((lane >> 4) << 3)) * 2;
            #pragma unroll
            for (int mt = 0; mt < WMT; mt++) {
                LDSM_X4(ah4[mt][0],ah4[mt][1],ah4[mt][2],ah4[mt][3],
                        ab + aoff + mt*16*TSTR*2);
            }
            int boff = ((n0w + ((lane >> 4) << 3) + (lane & 7))*TSTR +
                        ks*16 + (((lane >> 3) & 1) << 3)) * 2;
            #pragma unroll
            for (int nt2 = 0; nt2 < 4; nt2++) {
                uint32_t b4[4];
                LDSM_X4(b4[0],b4[1],b4[2],b4[3], bbb + boff + nt2*16*TSTR*2);
                uint32_t b01[2]={b4[0],b4[1]}, b23[2]={b4[2],b4[3]};
                #pragma unroll
                for (int mt = 0; mt < WMT; mt++) {
                    MMA16816(acc[mt][2*nt2],   ah4[mt], b01);
                    MMA16816(acc[mt][2*nt2+1], ah4[mt], b23);
                }
            }
        }
    }

    // epilogue
    #pragma unroll
    for (int mt = 0; mt < WMT; mt++) {
        int r0 = row0 + m0w + mt*16 + (lane >> 2);
        #pragma unroll
        for (int nt = 0; nt < 8; nt++) {
            int col = bn0 + n0w + nt*8 + ((lane & 3) << 1);
            float2 v0 = make_float2(acc[mt][nt][0], acc[mt][nt][1]);
            float2 v1 = make_float2(acc[mt][nt][2], acc[mt][nt][3]);
            if (fuse != 3) {
                float2 bv = *(const float2*)(bias + col);
                v0.x += bv.x; v0.y += bv.y;
                v1.x += bv.x; v1.y += bv.y;
            }
            if (fuse == 4) {
                hf* dst;
                int c2 = col;
                if (col < DD)            { dst = Ch; }
                else if (col < 2*DD)     { dst = Kb; c2 = col - DD; }
                else                     { dst = Vb; c2 = col - 2*DD; }
                *(uint32_t*)(dst + (size_t)r0*DD + c2)     = pack2h(v0.x, v0.y);
                *(uint32_t*)(dst + (size_t)(r0+8)*DD + c2) = pack2h(v1.x, v1.y);
                continue;
            }
            if (fuse == 1) {
                v0.x = 0.5f*v0.x*(1.0f + erff(v0.x*0.7071067811865475f));
                v0.y = 0.5f*v0.y*(1.0f + erff(v0.y*0.7071067811865475f));
                v1.x = 0.5f*v1.x*(1.0f + erff(v1.x*0.7071067811865475f));
                v1.y = 0.5f*v1.y*(1.0f + erff(v1.y*0.7071067811865475f));
                *(uint32_t*)(Ch + (size_t)r0*Nd + col)     = pack2h(v0.x, v0.y);
                *(uint32_t*)(Ch + (size_t)(r0+8)*Nd + col) = pack2h(v1.x, v1.y);
                continue;
            }
            if (fuse == 2) {
                float2 r0v = *(const float2*)(res + (size_t)r0*Nd + col);
                float2 r1v = *(const float2*)(res + (size_t)(r0+8)*Nd + col);
                v0.x += r0v.x; v0.y += r0v.y;
                v1.x += r1v.x; v1.y += r1v.y;
            }
            *(float2*)(C + (size_t)r0*Nd + col)     = v0;
            *(float2*)(C + (size_t)(r0+8)*Nd + col) = v1;
        }
    }
}

#define GS256 110592
#define GS128 73728

// ---------------- tensor-core flash attention (fp16, single-pass S) ----------
// S = Q K (both fp16); PV single pass. K/V double-buffered, ONE sync per tile.
#define ATQ 128
#define ATK 64
#define SQ  0
#define SK0 9216
#define ATTN_SMEM (27648*2)

__global__ __launch_bounds__(256, 2) void attn_kernel(
    const hf* __restrict__ qb,
    const hf* __restrict__ kb, const hf* __restrict__ vb,
    hf* __restrict__ oh)
{
    extern __shared__ hf smatt[];
    hf* sm = smatt;
    uint32_t smb = smem_u32(sm);

    int q0 = blockIdx.x * ATQ;
    int hh = blockIdx.y;
    int bb = blockIdx.z;
    int bbLL = bb * LL;
    int hoff = hh * HDD;

    int tid = threadIdx.x, lane = tid & 31, wid = tid >> 5;
    int wrow0 = q0 + wid*16;

    // load Q tile (128x64 fp16)
    #pragma unroll
    for (int p = 0; p < 2; p++) {
        int id = tid + (p << 8);
        int r  = id >> 2;
        int c8 = (id & 3) << 4;
        size_t g = (size_t)(bbLL + q0 + r)*DD + hoff + c8;
        *(uint4*)(sm + SQ + r*TSTR + c8)     = *(const uint4*)(qb + g);
        *(uint4*)(sm + SQ + r*TSTR + c8 + 8) = *(const uint4*)(qb + g + 8);
    }

    auto load_kv = [&](int t, int buf) {
        int k0 = t * ATK;
        uint32_t sk = smb + (SK0 + buf*9216)*2;
        uint32_t sv = sk + 4608*2;
        #pragma unroll
        for (int p = 0; p < 2; p++) {
            int id = tid + (p << 8);
            int r  = id >> 3;
            int c8 = (id & 7) << 3;
            size_t g = (size_t)(bbLL + k0 + r)*DD + hoff + c8;
            CP16(sk + (r*TSTR + c8)*2, kb + g);
            CP16(sv + (r*TSTR + c8)*2, vb + g);
        }
    };

    float Oa[8][4];
    #pragma unroll
    for (int i = 0; i < 8; i++)
        #pragma unroll
        for (int j = 0; j < 4; j++) Oa[i][j] = 0.f;
    float m0 = -1e30f, m1 = -1e30f, l0s = 0.f, l1s = 0.f;

    int qfb = ((wid*16 + (lane & 15))*TSTR + ((lane >> 4) << 3)) * 2;
    int krow = ((lane >> 4) << 3) + (lane & 7);
    int kcol = (((lane >> 3) & 1) << 3);
    int vrow = (((lane >> 3) & 1) << 3) + (lane & 7);
    int vcol = ((lane >> 4) << 3);
    int mr   = lane >> 2;
    int mc2  = (lane & 3) << 1;

    int ntiles = (q0 + ATQ) / ATK;
    load_kv(0, 0);
    CP_COMMIT();

    for (int t = 0; t < ntiles; t++) {
        int k0 = t * ATK;
        CP_WAIT0();            // tile t landed (also first-iter Q visibility)
        __syncthreads();       // prior reads of buf (t+1)&1 done
        if (t + 1 < ntiles) {
            load_kv(t+1, (t+1) & 1);
            CP_COMMIT();
        }

        if (k0 <= wrow0 + 15) {
            uint32_t skb = smb + (SK0 + (t&1)*9216)*2;
            uint32_t svb = skb + 4608*2;

            // ---- S = Q K ----
            float Sa[8][4];
            #pragma unroll
            for (int i = 0; i < 8; i++)
                #pragma unroll
                for (int j = 0; j < 4; j++) Sa[i][j] = 0.f;

            #pragma unroll
            for (int ks = 0; ks < 4; ks++) {
                uint32_t qf[4];
                LDSM_X4(qf[0],qf[1],qf[2],qf[3], smb + qfb + ks*32);
                #pragma unroll
                for (int np = 0; np < 4; np++) {
                    uint32_t kf[4];
                    LDSM_X4(kf[0],kf[1],kf[2],kf[3],
                            skb + ((np*16 + krow)*TSTR + kcol)*2 + ks*32);
                    uint32_t b01[2] = {kf[0],kf[1]}, b23[2] = {kf[2],kf[3]};
                    MMA16816(Sa[2*np],   qf, b01);
                    MMA16816(Sa[2*np+1], qf, b23);
                }
            }

            // scale + causal mask
            #pragma unroll
            for (int nt = 0; nt < 8; nt++)
                #pragma unroll
                for (int j = 0; j < 4; j++) Sa[nt][j] *= 0.125f;
            if (k0 + 63 > wrow0) {
                int r0g = wrow0 + mr, r1g = r0g + 8;
                #pragma unroll
                for (int nt = 0; nt < 8; nt++) {
                    int col = k0 + nt*8 + mc2;
                    if (col   > r0g) Sa[nt][0] = -1e30f;
                    if (col+1 > r0g) Sa[nt][1] = -1e30f;
                    if (col   > r1g) Sa[nt][2] = -1e30f;
                    if (col+1 > r1g) Sa[nt][3] = -1e30f;
                }
            }

            // ---- online softmax in registers ----
            float rx0 = -1e30f, rx1 = -1e30f;
            #pragma unroll
            for (int nt = 0; nt < 8; nt++) {
                rx0 = fmaxf(rx0, fmaxf(Sa[nt][0], Sa[nt][1]));
                rx1 = fmaxf(rx1, fmaxf(Sa[nt][2], Sa[nt][3]));
            }
            rx0 = fmaxf(rx0, __shfl_xor_sync(0xffffffffu, rx0, 1));
            rx0 = fmaxf(rx0, __shfl_xor_sync(0xffffffffu, rx0, 2));
            rx1 = fmaxf(rx1, __shfl_xor_sync(0xffffffffu, rx1, 1));
            rx1 = fmaxf(rx1, __shfl_xor_sync(0xffffffffu, rx1, 2));
            float mn0 = fmaxf(m0, rx0), mn1 = fmaxf(m1, rx1);
            float a0 = __expf(m0 - mn0), a1 = __expf(m1 - mn1);
            float s0 = 0.f, s1 = 0.f;
            #pragma unroll
            for (int nt = 0; nt < 8; nt++) {
                Sa[nt][0] = __expf(Sa[nt][0] - mn0);
                Sa[nt][1] = __expf(Sa[nt][1] - mn0);
                Sa[nt][2] = __expf(Sa[nt][2] - mn1);
                Sa[nt][3] = __expf(Sa[nt][3] - mn1);
                s0 += Sa[nt][0] + Sa[nt][1];
                s1 += Sa[nt][2] + Sa[nt][3];
            }
            s0 += __shfl_xor_sync(0xffffffffu, s0, 1);
            s0 += __shfl_xor_sync(0xffffffffu, s0, 2);
            s1 += __shfl_xor_sync(0xffffffffu, s1, 1);
            s1 += __shfl_xor_sync(0xffffffffu, s1, 2);
            l0s = l0s*a0 + s0;  l1s = l1s*a1 + s1;
            m0 = mn0; m1 = mn1;
            #pragma unroll
            for (int nt = 0; nt < 8; nt++) {
                Oa[nt][0] *= a0; Oa[nt][1] *= a0;
                Oa[nt][2] *= a1; Oa[nt][3] *= a1;
            }

            // ---- O += P V ----
            #pragma unroll
            for (int ks = 0; ks < 4; ks++) {
                uint32_t ph[4];
                ph[0] = pack2h(Sa[2*ks][0],   Sa[2*ks][1]);
                ph[1] = pack2h(Sa[2*ks][2],   Sa[2*ks][3]);
                ph[2] = pack2h(Sa[2*ks+1][0], Sa[2*ks+1][1]);
                ph[3] = pack2h(Sa[2*ks+1][2], Sa[2*ks+1][3]);
                #pragma unroll
                for (int np = 0; np < 4; np++) {
                    uint32_t vf[4];
                    LDSM_X4_T(vf[0],vf[1],vf[2],vf[3],
                              svb + ((ks*16 + vrow)*TSTR + np*16 + vcol)*2);
                    uint32_t b01[2] = {vf[0],vf[1]}, b23[2] = {vf[2],vf[3]};
                    MMA16816(Oa[2*np],   ph, b01);
                    MMA16816(Oa[2*np+1], ph, b23);
                }
            }
        }
    }

    // ---- write output (fp16; out-proj is single-pass) ----
    float inv0 = 1.0f / l0s, inv1 = 1.0f / l1s;
    size_t r0g = (size_t)bbLL + wrow0 + mr;
    size_t r1g = r0g + 8;
    int cb = hoff + mc2;
    #pragma unroll
    for (int nt = 0; nt < 8; nt++) {
        int col = cb + nt*8;
        *(uint32_t*)(oh + r0g*DD + col) = pack2h(Oa[nt][0]*inv0, Oa[nt][1]*inv0);
        *(uint32_t*)(oh + r1g*DD + col) = pack2h(Oa[nt][2]*inv1, Oa[nt][3]*inv1);
    }
}

// ---------------- launcher ----------------------------------------------------
extern "C" void kernel_launch(void* const* d_in, const int* in_sizes, int n_in,
                              void* d_out, int out_size)
{
    const int*   x     = (const int*)  d_in[0];
    const float* tok   = (const float*)d_in[1];
    const float* pos   = (const float*)d_in[2];
    const float* ln1g  = (const float*)d_in[3];
    const float* ln1b  = (const float*)d_in[4];
    const float* qkvw  = (const float*)d_in[5];
    const float* qkvb  = (const float*)d_in[6];
    const float* outw  = (const float*)d_in[7];
    const float* outb  = (const float*)d_in[8];
    const float* ln2g  = (const float*)d_in[9];
    const float* ln2b  = (const float*)d_in[10];
    const float* w1    = (const float*)d_in[11];
    const float* b1    = (const float*)d_in[12];
    const float* w2    = (const float*)d_in[13];
    const float* b2    = (const float*)d_in[14];
    const float* lnfg  = (const float*)d_in[15];
    const float* lnfb  = (const float*)d_in[16];
    const float* headw = (const float*)d_in[17];
    float* out = (float*)d_out;

    float *h;
    hf *xh, *mh, *w, *qb, *kb, *vb;
    cudaGetSymbolAddress((void**)&h,   g_h);
    cudaGetSymbolAddress((void**)&xh,  g_xh);
    cudaGetSymbolAddress((void**)&mh,  g_mh);
    cudaGetSymbolAddress((void**)&w,   g_w);
    cudaGetSymbolAddress((void**)&qb,  g_qb);
    cudaGetSymbolAddress((void**)&kb,  g_kb);
    cudaGetSymbolAddress((void**)&vb,  g_vb);

    cudaFuncSetAttribute(attn_kernel,
        cudaFuncAttributeMaxDynamicSharedMemorySize, ATTN_SMEM);
    cudaFuncSetAttribute(tcgemm<256>,
        cudaFuncAttributeMaxDynamicSharedMemorySize, GS256);
    cudaFuncSetAttribute(tcgemm<128>,
        cudaFuncAttributeMaxDynamicSharedMemorySize, GS128);

    // weight prep: transpose [K,N] -> [N,K] + fp16 convert (layer-batched)
    dim3 tb(32, 8);
    tconv_kernel<<<dim3(1536/32, 512/32, NLL), tb>>>(
        qkvw, w + W_QKV0, 512, 1536, (size_t)DD*3*DD, 786432);
    tconv_kernel<<<dim3(512/32, 512/32, NLL), tb>>>(
        outw, w + W_OUT0, 512, 512, (size_t)DD*DD, 262144);
    tconv_kernel<<<dim3(2048/32, 512/32, NLL), tb>>>(
        w1, w + W_W10, 512, 2048, (size_t)DD*DMM, 1048576);
    tconv_kernel<<<dim3(512/32, 2048/32, NLL), tb>>>(
        w2, w + W_W20, 2048, 512, (size_t)DMM*DD, 1048576);
    tconv_kernel<<<dim3(32000/32, 512/32, 1), tb>>>(
        headw, w + W_HEAD, 512, 32000, 0, 0);

    embed_kernel<<<(MM*DD)/256, 256>>>(x, tok, pos, h);

    for (int i = 0; i < NLL; i++) {
        // attn block
        layernorm_kernel<<<MM, 256>>>(h, ln1g + i*DD, ln1b + i*DD, xh);
        tcgemm<128><<<dim3(1536/128, MM/128), 256, GS128>>>(
            xh, w + W_QKV0 + (size_t)i*786432,
            qkvb + (size_t)i*3*DD, nullptr, nullptr, qb, kb, vb,
            512, 1536, 4);
        attn_kernel<<<dim3(LL/ATQ, NHH, BB), 256, ATTN_SMEM>>>(
            qb, kb, vb, xh);
        tcgemm<128><<<dim3(512/128, MM/128), 256, GS128>>>(
            xh, w + W_OUT0 + (size_t)i*262144,
            outb + (size_t)i*DD, h, h, nullptr, nullptr, nullptr,
            512, 512, 2);
        // mlp block
        layernorm_kernel<<<MM, 256>>>(h, ln2g + i*DD, ln2b + i*DD, xh);
        tcgemm<256><<<dim3(2048/256, MM/128), 256, GS256>>>(
            xh, w + W_W10 + (size_t)i*1048576,
            b1 + (size_t)i*DMM, nullptr, nullptr, mh, nullptr, nullptr,
            512, 2048, 1);
        tcgemm<128><<<dim3(512/128, MM/128), 256, GS128>>>(
            mh, w + W_W20 + (size_t)i*1048576,
            b2 + (size_t)i*DD, h, h, nullptr, nullptr, nullptr,
            2048, 512, 2);
    }

    layernorm_kernel<<<MM, 256>>>(h, lnfg, lnfb, xh);
    tcgemm<256><<<dim3(VV/256, MM/128), 256, GS256>>>(
        xh, w + W_HEAD,
        nullptr, nullptr, out, nullptr, nullptr, nullptr,
        512, VV, 3);
}

// round 17
// speedup vs baseline: 1.7138x; 1.0766x over previous
#include <cuda_runtime.h>
#include <cuda_fp16.h>
#include <math.h>
#include <stdint.h>

typedef __half hf;

// Problem dims
#define BB 2
#define LL 2048
#define DD 512
#define NHH 8
#define NLL 4
#define DMM 2048
#define VV 32000
#define HDD 64
#define MM (BB*LL)          // 4096 rows

// ---------------- PTX helpers ------------------------------------------------
__device__ __forceinline__ uint32_t smem_u32(const void* p) {
    uint32_t a;
    asm("{ .reg .u64 t; cvta.to.shared.u64 t, %1; cvt.u32.u64 %0, t; }"
        : "=r"(a) : "l"(p));
    return a;
}

#define LDSM_X4(r0,r1,r2,r3,addr) \
    asm volatile("ldmatrix.sync.aligned.m8n8.x4.shared.b16 {%0,%1,%2,%3}, [%4];" \
        : "=r"(r0), "=r"(r1), "=r"(r2), "=r"(r3) : "r"(addr))
#define LDSM_X4_T(r0,r1,r2,r3,addr) \
    asm volatile("ldmatrix.sync.aligned.m8n8.x4.trans.shared.b16 {%0,%1,%2,%3}, [%4];" \
        : "=r"(r0), "=r"(r1), "=r"(r2), "=r"(r3) : "r"(addr))
#define MMA16816(d, a, b) \
    asm volatile("mma.sync.aligned.m16n8k16.row.col.f32.f16.f16.f32 " \
        "{%0,%1,%2,%3}, {%4,%5,%6,%7}, {%8,%9}, {%0,%1,%2,%3};" \
        : "+f"((d)[0]), "+f"((d)[1]), "+f"((d)[2]), "+f"((d)[3]) \
        : "r"((a)[0]), "r"((a)[1]), "r"((a)[2]), "r"((a)[3]), \
          "r"((b)[0]), "r"((b)[1]))
#define CP16(dst, src) \
    asm volatile("cp.async.cg.shared.global [%0], [%1], 16;" :: "r"(dst), "l"(src))
#define CP_COMMIT() asm volatile("cp.async.commit_group;" ::: "memory")
#define CP_WAIT0()  asm volatile("cp.async.wait_group 0;" ::: "memory")

__device__ __forceinline__ uint32_t pack2h(float a, float b) {
    __half2 p = __floats2half2_rn(a, b);
    return *(uint32_t*)&p;
}

// ---------------- scratch (device globals) -----------------------------------
__device__ float g_h  [MM*DD];        // residual stream
__device__ hf    g_xh [MM*DD];        // activation (LN out / attn out)
__device__ hf    g_mh [MM*DMM];       // mlp hidden (fp16)
__device__ hf    g_qb [MM*DD];        // attention Q, K, V (fp16)
__device__ hf    g_kb [MM*DD];
__device__ hf    g_vb [MM*DD];

// transposed fp16 weights [N,K]
#define W_QKV0 0
#define W_OUT0 3145728
#define W_W10  4194304
#define W_W20  8388608
#define W_HEAD 12582912
#define WTOT   28966912
__device__ hf g_w[WTOT];

// ---------------- embedding --------------------------------------------------
__global__ void embed_kernel(const int* __restrict__ x,
                             const float* __restrict__ tok,
                             const float* __restrict__ pos,
                             float* __restrict__ h)
{
    int i = blockIdx.x * blockDim.x + threadIdx.x;
    int d  = i & (DD-1);
    int bl = i / DD;
    int l  = bl & (LL-1);
    h[i] = tok[(size_t)x[bl]*DD + d] + pos[l*DD + d];
}

// ---------------- layernorm (fp16 output) ------------------------------------
__global__ __launch_bounds__(256) void layernorm_kernel(
    const float* __restrict__ x, const float* __restrict__ g,
    const float* __restrict__ b, hf* __restrict__ yh)
{
    __shared__ float red[16];
    __shared__ float stats[2];
    int row = blockIdx.x;
    int tid = threadIdx.x;
    const float2* xr = (const float2*)(x + (size_t)row*DD);
    float2 v = xr[tid];
    float s = v.x + v.y;
    float q = v.x*v.x + v.y*v.y;
    #pragma unroll
    for (int o = 16; o; o >>= 1) {
        s += __shfl_down_sync(0xffffffffu, s, o);
        q += __shfl_down_sync(0xffffffffu, q, o);
    }
    int w = tid >> 5;
    if ((tid & 31) == 0) { red[w] = s; red[w+8] = q; }
    __syncthreads();
    if (tid < 32) {
        s = (tid < 8) ? red[tid]   : 0.f;
        q = (tid < 8) ? red[tid+8] : 0.f;
        #pragma unroll
        for (int o = 4; o; o >>= 1) {
            s += __shfl_down_sync(0xffffffffu, s, o);
            q += __shfl_down_sync(0xffffffffu, q, o);
        }
        if (tid == 0) {
            float mu  = s * (1.0f/DD);
            float var = q * (1.0f/DD) - mu*mu;
            stats[0] = mu;
            stats[1] = rsqrtf(var + 1e-5f);
        }
    }
    __syncthreads();
    float mu = stats[0], inv = stats[1];
    float2 gg = ((const float2*)g)[tid];
    float2 bb = ((const float2*)b)[tid];
    float ox = (v.x - mu)*inv*gg.x + bb.x;
    float oy = (v.y - mu)*inv*gg.y + bb.y;
    *(uint32_t*)(yh + (size_t)row*DD + 2*tid) = pack2h(ox, oy);
}

// ------- weight transpose+convert: [K,N] -> [N,K] fp16, layer-batched --------
__global__ __launch_bounds__(256) void tconv_kernel(
    const float* __restrict__ in, hf* __restrict__ w, int K, int N,
    size_t inStride, size_t outStride)
{
    __shared__ float t[32][33];
    in += blockIdx.z * inStride;
    w  += blockIdx.z * outStride;
    int n0 = blockIdx.x * 32, k0 = blockIdx.y * 32;
    int tx = threadIdx.x, ty = threadIdx.y;
    #pragma unroll
    for (int i = ty; i < 32; i += 8)
        t[i][tx] = in[(size_t)(k0+i)*N + n0 + tx];
    __syncthreads();
    #pragma unroll
    for (int i = ty; i < 32; i += 8)
        w[(size_t)(n0+i)*K + k0 + tx] = __float2half_rn(t[tx][i]);
}

// ---------------- fp16 GEMM, 2-stage cp.async, ONE sync per chunk ------------
// CTA tile BM x BN, NT threads, warp tiles 32x64 or 64x64.
// Shapes: <128,128,256> 2 CTA/SM; <64,128,128> 4 CTA/SM; <128,256,256> 1 CTA/SM
// fuse: 0=+bias->f32, 1=gelu(+bias)->fp16, 2=+bias+res->f32, 3=plain->f32,
//       4=+bias-> split qkv: Q/K/V fp16 (stride DD)
#define TSTR 72   // smem row stride in fp16 elems (144B: conflict-free ldmatrix)

template<int BM, int BN, int NT>
__global__ __launch_bounds__(NT, BM == 64 ? 4 : (BN == 128 ? 2 : 1)) void tcgemm(
    const hf* __restrict__ Ahp,
    const hf* __restrict__ Bp,
    const float* __restrict__ bias, const float* __restrict__ res,
    float* __restrict__ C, hf* __restrict__ Ch,
    hf* __restrict__ Kb, hf* __restrict__ Vb,
    int Kd, int Nd, int fuse)
{
    constexpr int NWARP = NT/32;
    constexpr int NWN = BN/64;          // warps in N dir
    constexpr int NWM = NWARP/NWN;      // warps in M dir
    constexpr int WMT = (BM/NWM)/16;    // m16 tiles per warp
    constexpr int AE = BM*TSTR;
    constexpr int BE = BN*TSTR;
    constexpr int STAGE = AE + BE;      // elems per stage
    constexpr int AP = BM*8/NT;
    constexpr int BP = BN*8/NT;

    extern __shared__ hf sm[];
    uint32_t smb = smem_u32(sm);

    int tid = threadIdx.x, lane = tid & 31, wid = tid >> 5;
    int m0w = (wid / NWN) * (WMT*16);
    int n0w = (wid % NWN) * 64;
    int bn0  = blockIdx.x * BN;
    int row0 = blockIdx.y * BM;

    float acc[WMT][8][4];
    #pragma unroll
    for (int i = 0; i < WMT; i++)
        #pragma unroll
        for (int j = 0; j < 8; j++)
            #pragma unroll
            for (int k = 0; k < 4; k++) acc[i][j][k] = 0.f;

    int kseg = Kd >> 6;

    auto load_stage = [&](int buf, int kk) {
        uint32_t sb = smb + buf*STAGE*2;
        #pragma unroll
        for (int p = 0; p < AP; p++) {
            int id = tid + p*NT; int r = id>>3, cc = (id&7)<<3;
            CP16(sb + (r*TSTR + cc)*2,
                 Ahp + (size_t)(row0+r)*Kd + kk + cc);
        }
        #pragma unroll
        for (int p = 0; p < BP; p++) {
            int id = tid + p*NT; int r = id>>3, cc = (id&7)<<3;
            CP16(sb + (AE + r*TSTR + cc)*2,
                 Bp + (size_t)(bn0+r)*Kd + kk + cc);
        }
    };

    load_stage(0, 0);
    CP_COMMIT();

    for (int c = 0; c < kseg; c++) {
        CP_WAIT0();            // stage c landed
        __syncthreads();       // visible to all; prior reads of buf (c+1)&1 done
        if (c + 1 < kseg) {
            load_stage((c+1)&1, (c+1)<<6);
            CP_COMMIT();
        }

        uint32_t ab  = smb + (c&1)*STAGE*2;
        uint32_t bbb = ab + AE*2;

        #pragma unroll
        for (int ks = 0; ks < 4; ks++) {
            uint32_t ah4[WMT][4];
            int aoff = ((m0w + (lane & 15))*TSTR + ks*16 + ((lane >> 4) << 3)) * 2;
            #pragma unroll
            for (int mt = 0; mt < WMT; mt++) {
                LDSM_X4(ah4[mt][0],ah4[mt][1],ah4[mt][2],ah4[mt][3],
                        ab + aoff + mt*16*TSTR*2);
            }
            int boff = ((n0w + ((lane >> 4) << 3) + (lane & 7))*TSTR +
                        ks*16 + (((lane >> 3) & 1) << 3)) * 2;
            #pragma unroll
            for (int nt2 = 0; nt2 < 4; nt2++) {
                uint32_t b4[4];
                LDSM_X4(b4[0],b4[1],b4[2],b4[3], bbb + boff + nt2*16*TSTR*2);
                uint32_t b01[2]={b4[0],b4[1]}, b23[2]={b4[2],b4[3]};
                #pragma unroll
                for (int mt = 0; mt < WMT; mt++) {
                    MMA16816(acc[mt][2*nt2],   ah4[mt], b01);
                    MMA16816(acc[mt][2*nt2+1], ah4[mt], b23);
                }
            }
        }
    }

    // epilogue
    #pragma unroll
    for (int mt = 0; mt < WMT; mt++) {
        int r0 = row0 + m0w + mt*16 + (lane >> 2);
        #pragma unroll
        for (int nt = 0; nt < 8; nt++) {
            int col = bn0 + n0w + nt*8 + ((lane & 3) << 1);
            float2 v0 = make_float2(acc[mt][nt][0], acc[mt][nt][1]);
            float2 v1 = make_float2(acc[mt][nt][2], acc[mt][nt][3]);
            if (fuse != 3) {
                float2 bv = *(const float2*)(bias + col);
                v0.x += bv.x; v0.y += bv.y;
                v1.x += bv.x; v1.y += bv.y;
            }
            if (fuse == 4) {
                hf* dst;
                int c2 = col;
                if (col < DD)            { dst = Ch; }
                else if (col < 2*DD)     { dst = Kb; c2 = col - DD; }
                else                     { dst = Vb; c2 = col - 2*DD; }
                *(uint32_t*)(dst + (size_t)r0*DD + c2)     = pack2h(v0.x, v0.y);
                *(uint32_t*)(dst + (size_t)(r0+8)*DD + c2) = pack2h(v1.x, v1.y);
                continue;
            }
            if (fuse == 1) {
                v0.x = 0.5f*v0.x*(1.0f + erff(v0.x*0.7071067811865475f));
                v0.y = 0.5f*v0.y*(1.0f + erff(v0.y*0.7071067811865475f));
                v1.x = 0.5f*v1.x*(1.0f + erff(v1.x*0.7071067811865475f));
                v1.y = 0.5f*v1.y*(1.0f + erff(v1.y*0.7071067811865475f));
                *(uint32_t*)(Ch + (size_t)r0*Nd + col)     = pack2h(v0.x, v0.y);
                *(uint32_t*)(Ch + (size_t)(r0+8)*Nd + col) = pack2h(v1.x, v1.y);
                continue;
            }
            if (fuse == 2) {
                float2 r0v = *(const float2*)(res + (size_t)r0*Nd + col);
                float2 r1v = *(const float2*)(res + (size_t)(r0+8)*Nd + col);
                v0.x += r0v.x; v0.y += r0v.y;
                v1.x += r1v.x; v1.y += r1v.y;
            }
            *(float2*)(C + (size_t)r0*Nd + col)     = v0;
            *(float2*)(C + (size_t)(r0+8)*Nd + col) = v1;
        }
    }
}

#define GSA 73728    // <128,128,256>
#define GSB 55296    // <64,128,128>
#define GSC 110592   // <128,256,256>

// ---------------- tensor-core flash attention (fp16, triangle-paired) --------
// Each CTA handles q-blocks bx and (NQB-1-bx): constant 34 k-tiles per CTA.
#define ATQ 128
#define ATK 64
#define NQB (LL/ATQ)   // 16
#define SQ  0
#define SK0 9216
#define ATTN_SMEM (27648*2)

__global__ __launch_bounds__(256, 2) void attn_kernel(
    const hf* __restrict__ qb,
    const hf* __restrict__ kb, const hf* __restrict__ vb,
    hf* __restrict__ oh)
{
    extern __shared__ hf smatt[];
    hf* sm = smatt;
    uint32_t smb = smem_u32(sm);

    int hh = blockIdx.y;
    int bb = blockIdx.z;
    int bbLL = bb * LL;
    int hoff = hh * HDD;

    int tid = threadIdx.x, lane = tid & 31, wid = tid >> 5;

    int qfb = ((wid*16 + (lane & 15))*TSTR + ((lane >> 4) << 3)) * 2;
    int krow = ((lane >> 4) << 3) + (lane & 7);
    int kcol = (((lane >> 3) & 1) << 3);
    int vrow = (((lane >> 3) & 1) << 3) + (lane & 7);
    int vcol = ((lane >> 4) << 3);
    int mr   = lane >> 2;
    int mc2  = (lane & 3) << 1;

    auto load_kv = [&](int t, int buf) {
        int k0 = t * ATK;
        uint32_t sk = smb + (SK0 + buf*9216)*2;
        uint32_t sv = sk + 4608*2;
        #pragma unroll
        for (int p = 0; p < 2; p++) {
            int id = tid + (p << 8);
            int r  = id >> 3;
            int c8 = (id & 7) << 3;
            size_t g = (size_t)(bbLL + k0 + r)*DD + hoff + c8;
            CP16(sk + (r*TSTR + c8)*2, kb + g);
            CP16(sv + (r*TSTR + c8)*2, vb + g);
        }
    };

    #pragma unroll 1
    for (int phase = 0; phase < 2; phase++) {
        int qblk = phase ? (NQB - 1 - (int)blockIdx.x) : (int)blockIdx.x;
        int q0 = qblk * ATQ;
        int wrow0 = q0 + wid*16;

        __syncthreads();   // prior phase's smem reads complete before overwrite

        // load Q tile (128x64 fp16)
        #pragma unroll
        for (int p = 0; p < 2; p++) {
            int id = tid + (p << 8);
            int r  = id >> 2;
            int c8 = (id & 3) << 4;
            size_t g = (size_t)(bbLL + q0 + r)*DD + hoff + c8;
            *(uint4*)(sm + SQ + r*TSTR + c8)     = *(const uint4*)(qb + g);
            *(uint4*)(sm + SQ + r*TSTR + c8 + 8) = *(const uint4*)(qb + g + 8);
        }

        float Oa[8][4];
        #pragma unroll
        for (int i = 0; i < 8; i++)
            #pragma unroll
            for (int j = 0; j < 4; j++) Oa[i][j] = 0.f;
        float m0 = -1e30f, m1 = -1e30f, l0s = 0.f, l1s = 0.f;

        int ntiles = (q0 + ATQ) / ATK;
        load_kv(0, 0);
        CP_COMMIT();

        for (int t = 0; t < ntiles; t++) {
            int k0 = t * ATK;
            CP_WAIT0();            // tile t landed (also Q visibility)
            __syncthreads();       // prior reads of buf (t+1)&1 done
            if (t + 1 < ntiles) {
                load_kv(t+1, (t+1) & 1);
                CP_COMMIT();
            }

            if (k0 <= wrow0 + 15) {
                uint32_t skb = smb + (SK0 + (t&1)*9216)*2;
                uint32_t svb = skb + 4608*2;

                // ---- S = Q K ----
                float Sa[8][4];
                #pragma unroll
                for (int i = 0; i < 8; i++)
                    #pragma unroll
                    for (int j = 0; j < 4; j++) Sa[i][j] = 0.f;

                #pragma unroll
                for (int ks = 0; ks < 4; ks++) {
                    uint32_t qf[4];
                    LDSM_X4(qf[0],qf[1],qf[2],qf[3], smb + qfb + ks*32);
                    #pragma unroll
                    for (int np = 0; np < 4; np++) {
                        uint32_t kf[4];
                        LDSM_X4(kf[0],kf[1],kf[2],kf[3],
                                skb + ((np*16 + krow)*TSTR + kcol)*2 + ks*32);
                        uint32_t b01[2] = {kf[0],kf[1]}, b23[2] = {kf[2],kf[3]};
                        MMA16816(Sa[2*np],   qf, b01);
                        MMA16816(Sa[2*np+1], qf, b23);
                    }
                }

                // scale + causal mask
                #pragma unroll
                for (int nt = 0; nt < 8; nt++)
                    #pragma unroll
                    for (int j = 0; j < 4; j++) Sa[nt][j] *= 0.125f;
                if (k0 + 63 > wrow0) {
                    int r0g = wrow0 + mr, r1g = r0g + 8;
                    #pragma unroll
                    for (int nt = 0; nt < 8; nt++) {
                        int col = k0 + nt*8 + mc2;
                        if (col   > r0g) Sa[nt][0] = -1e30f;
                        if (col+1 > r0g) Sa[nt][1] = -1e30f;
                        if (col   > r1g) Sa[nt][2] = -1e30f;
                        if (col+1 > r1g) Sa[nt][3] = -1e30f;
                    }
                }

                // ---- online softmax in registers ----
                float rx0 = -1e30f, rx1 = -1e30f;
                #pragma unroll
                for (int nt = 0; nt < 8; nt++) {
                    rx0 = fmaxf(rx0, fmaxf(Sa[nt][0], Sa[nt][1]));
                    rx1 = fmaxf(rx1, fmaxf(Sa[nt][2], Sa[nt][3]));
                }
                rx0 = fmaxf(rx0, __shfl_xor_sync(0xffffffffu, rx0, 1));
                rx0 = fmaxf(rx0, __shfl_xor_sync(0xffffffffu, rx0, 2));
                rx1 = fmaxf(rx1, __shfl_xor_sync(0xffffffffu, rx1, 1));
                rx1 = fmaxf(rx1, __shfl_xor_sync(0xffffffffu, rx1, 2));
                float mn0 = fmaxf(m0, rx0), mn1 = fmaxf(m1, rx1);
                float a0 = __expf(m0 - mn0), a1 = __expf(m1 - mn1);
                float s0 = 0.f, s1 = 0.f;
                #pragma unroll
                for (int nt = 0; nt < 8; nt++) {
                    Sa[nt][0] = __expf(Sa[nt][0] - mn0);
                    Sa[nt][1] = __expf(Sa[nt][1] - mn0);
                    Sa[nt][2] = __expf(Sa[nt][2] - mn1);
                    Sa[nt][3] = __expf(Sa[nt][3] - mn1);
                    s0 += Sa[nt][0] + Sa[nt][1];
                    s1 += Sa[nt][2] + Sa[nt][3];
                }
                s0 += __shfl_xor_sync(0xffffffffu, s0, 1);
                s0 += __shfl_xor_sync(0xffffffffu, s0, 2);
                s1 += __shfl_xor_sync(0xffffffffu, s1, 1);
                s1 += __shfl_xor_sync(0xffffffffu, s1, 2);
                l0s = l0s*a0 + s0;  l1s = l1s*a1 + s1;
                m0 = mn0; m1 = mn1;
                #pragma unroll
                for (int nt = 0; nt < 8; nt++) {
                    Oa[nt][0] *= a0; Oa[nt][1] *= a0;
                    Oa[nt][2] *= a1; Oa[nt][3] *= a1;
                }

                // ---- O += P V ----
                #pragma unroll
                for (int ks = 0; ks < 4; ks++) {
                    uint32_t ph[4];
                    ph[0] = pack2h(Sa[2*ks][0],   Sa[2*ks][1]);
                    ph[1] = pack2h(Sa[2*ks][2],   Sa[2*ks][3]);
                    ph[2] = pack2h(Sa[2*ks+1][0], Sa[2*ks+1][1]);
                    ph[3] = pack2h(Sa[2*ks+1][2], Sa[2*ks+1][3]);
                    #pragma unroll
                    for (int np = 0; np < 4; np++) {
                        uint32_t vf[4];
                        LDSM_X4_T(vf[0],vf[1],vf[2],vf[3],
                                  svb + ((ks*16 + vrow)*TSTR + np*16 + vcol)*2);
                        uint32_t b01[2] = {vf[0],vf[1]}, b23[2] = {vf[2],vf[3]};
                        MMA16816(Oa[2*np],   ph, b01);
                        MMA16816(Oa[2*np+1], ph, b23);
                    }
                }
            }
        }

        // ---- write output (fp16) ----
        float inv0 = 1.0f / l0s, inv1 = 1.0f / l1s;
        size_t r0g = (size_t)bbLL + wrow0 + mr;
        size_t r1g = r0g + 8;
        int cb = hoff + mc2;
        #pragma unroll
        for (int nt = 0; nt < 8; nt++) {
            int col = cb + nt*8;
            *(uint32_t*)(oh + r0g*DD + col) = pack2h(Oa[nt][0]*inv0, Oa[nt][1]*inv0);
            *(uint32_t*)(oh + r1g*DD + col) = pack2h(Oa[nt][2]*inv1, Oa[nt][3]*inv1);
        }
    }
}

// ---------------- launcher ----------------------------------------------------
extern "C" void kernel_launch(void* const* d_in, const int* in_sizes, int n_in,
                              void* d_out, int out_size)
{
    const int*   x     = (const int*)  d_in[0];
    const float* tok   = (const float*)d_in[1];
    const float* pos   = (const float*)d_in[2];
    const float* ln1g  = (const float*)d_in[3];
    const float* ln1b  = (const float*)d_in[4];
    const float* qkvw  = (const float*)d_in[5];
    const float* qkvb  = (const float*)d_in[6];
    const float* outw  = (const float*)d_in[7];
    const float* outb  = (const float*)d_in[8];
    const float* ln2g  = (const float*)d_in[9];
    const float* ln2b  = (const float*)d_in[10];
    const float* w1    = (const float*)d_in[11];
    const float* b1    = (const float*)d_in[12];
    const float* w2    = (const float*)d_in[13];
    const float* b2    = (const float*)d_in[14];
    const float* lnfg  = (const float*)d_in[15];
    const float* lnfb  = (const float*)d_in[16];
    const float* headw = (const float*)d_in[17];
    float* out = (float*)d_out;

    float *h;
    hf *xh, *mh, *w, *qb, *kb, *vb;
    cudaGetSymbolAddress((void**)&h,   g_h);
    cudaGetSymbolAddress((void**)&xh,  g_xh);
    cudaGetSymbolAddress((void**)&mh,  g_mh);
    cudaGetSymbolAddress((void**)&w,   g_w);
    cudaGetSymbolAddress((void**)&qb,  g_qb);
    cudaGetSymbolAddress((void**)&kb,  g_kb);
    cudaGetSymbolAddress((void**)&vb,  g_vb);

    cudaFuncSetAttribute(attn_kernel,
        cudaFuncAttributeMaxDynamicSharedMemorySize, ATTN_SMEM);
    cudaFuncSetAttribute((const void*)tcgemm<128,128,256>,
        cudaFuncAttributeMaxDynamicSharedMemorySize, GSA);
    cudaFuncSetAttribute((const void*)tcgemm<64,128,128>,
        cudaFuncAttributeMaxDynamicSharedMemorySize, GSB);
    cudaFuncSetAttribute((const void*)tcgemm<128,256,256>,
        cudaFuncAttributeMaxDynamicSharedMemorySize, GSC);

    // weight prep: transpose [K,N] -> [N,K] + fp16 convert (layer-batched)
    dim3 tb(32, 8);
    tconv_kernel<<<dim3(1536/32, 512/32, NLL), tb>>>(
        qkvw, w + W_QKV0, 512, 1536, (size_t)DD*3*DD, 786432);
    tconv_kernel<<<dim3(512/32, 512/32, NLL), tb>>>(
        outw, w + W_OUT0, 512, 512, (size_t)DD*DD, 262144);
    tconv_kernel<<<dim3(2048/32, 512/32, NLL), tb>>>(
        w1, w + W_W10, 512, 2048, (size_t)DD*DMM, 1048576);
    tconv_kernel<<<dim3(512/32, 2048/32, NLL), tb>>>(
        w2, w + W_W20, 2048, 512, (size_t)DMM*DD, 1048576);
    tconv_kernel<<<dim3(32000/32, 512/32, 1), tb>>>(
        headw, w + W_HEAD, 512, 32000, 0, 0);

    embed_kernel<<<(MM*DD)/256, 256>>>(x, tok, pos, h);

    for (int i = 0; i < NLL; i++) {
        // attn block
        layernorm_kernel<<<MM, 256>>>(h, ln1g + i*DD, ln1b + i*DD, xh);
        tcgemm<128,128,256><<<dim3(1536/128, MM/128), 256, GSA>>>(
            xh, w + W_QKV0 + (size_t)i*786432,
            qkvb + (size_t)i*3*DD, nullptr, nullptr, qb, kb, vb,
            512, 1536, 4);
        attn_kernel<<<dim3(NQB/2, NHH, BB), 256, ATTN_SMEM>>>(
            qb, kb, vb, xh);
        tcgemm<64,128,128><<<dim3(512/128, MM/64), 128, GSB>>>(
            xh, w + W_OUT0 + (size_t)i*262144,
            outb + (size_t)i*DD, h, h, nullptr, nullptr, nullptr,
            512, 512, 2);
        // mlp block
        layernorm_kernel<<<MM, 256>>>(h, ln2g + i*DD, ln2b + i*DD, xh);
        tcgemm<128,128,256><<<dim3(2048/128, MM/128), 256, GSA>>>(
            xh, w + W_W10 + (size_t)i*1048576,
            b1 + (size_t)i*DMM, nullptr, nullptr, mh, nullptr, nullptr,
            512, 2048, 1);
        tcgemm<64,128,128><<<dim3(512/128, MM/64), 128, GSB>>>(
            mh, w + W_W20 + (size_t)i*1048576,
            b2 + (size_t)i*DD, h, h, nullptr, nullptr, nullptr,
            2048, 512, 2);
    }

    layernorm_kernel<<<MM, 256>>>(h, lnfg, lnfb, xh);
    tcgemm<128,256,256><<<dim3(VV/256, MM/128), 256, GSC>>>(
        xh, w + W_HEAD,
        nullptr, nullptr, out, nullptr, nullptr, nullptr,
        512, VV, 3);
}